// round 15
// baseline (speedup 1.0000x reference)
#include <cuda_runtime.h>
#include <cuda_fp16.h>
#include <math.h>
#include <stdint.h>

#define BB 4
#define NN 4096
#define MMCTX 4096
#define EE 512
#define HH 8
#define DD 64
#define ROWS_QK (BB * NN)          // 16384
#define ROWS_MLP (BB * MMCTX * HH) // 131072

typedef __half h16;
typedef __half2 h162;

__device__ __forceinline__ uint32_t smem_u32(const void* p) {
    uint32_t a;
    asm("{ .reg .u64 t; cvta.to.shared.u64 t, %1; cvt.u32.u64 %0, t; }"
        : "=r"(a) : "l"(p));
    return a;
}

#define SWZ128(b) ((b) ^ (((b) >> 3) & 0x70))

__device__ __forceinline__ void cp_async16(uint32_t dst, const void* src) {
    asm volatile("cp.async.cg.shared.global [%0], [%1], 16;\n"
                 :: "r"(dst), "l"(src));
}
#define CP_COMMIT() asm volatile("cp.async.commit_group;\n" ::: "memory")
#define CP_WAIT1() asm volatile("cp.async.wait_group 1;\n" ::: "memory")
#define CP_WAIT0() asm volatile("cp.async.wait_group 0;\n" ::: "memory")

__device__ __forceinline__ void ldmatrix_x4(uint32_t addr, uint32_t& r0,
                                            uint32_t& r1, uint32_t& r2,
                                            uint32_t& r3) {
    asm volatile("ldmatrix.sync.aligned.m8n8.x4.shared.b16 {%0,%1,%2,%3}, [%4];"
                 : "=r"(r0), "=r"(r1), "=r"(r2), "=r"(r3) : "r"(addr));
}

__device__ __forceinline__ void ldmatrix_x4t(uint32_t addr, uint32_t& r0,
                                             uint32_t& r1, uint32_t& r2,
                                             uint32_t& r3) {
    asm volatile(
        "ldmatrix.sync.aligned.m8n8.x4.trans.shared.b16 {%0,%1,%2,%3}, [%4];"
        : "=r"(r0), "=r"(r1), "=r"(r2), "=r"(r3) : "r"(addr));
}

__device__ __forceinline__ void mma16816(float* c, const uint32_t* a,
                                         const uint32_t* b) {
    asm volatile(
        "mma.sync.aligned.m16n8k16.row.col.f32.f16.f16.f32 "
        "{%0,%1,%2,%3}, {%4,%5,%6,%7}, {%8,%9}, {%0,%1,%2,%3};"
        : "+f"(c[0]), "+f"(c[1]), "+f"(c[2]), "+f"(c[3])
        : "r"(a[0]), "r"(a[1]), "r"(a[2]), "r"(a[3]), "r"(b[0]), "r"(b[1]));
}

// ===================== scratch =====================
__device__ h16 g_q16[ROWS_QK * EE];
__device__ h16 g_v16[ROWS_QK * EE];
__device__ h16 g_ka16[ROWS_MLP * DD];
__device__ float g_kv[BB * HH * DD * DD];
__device__ float g_ksum[BB * HH * DD];

__device__ h16 g_kact[ROWS_MLP * DD];
__device__ h16 g_attn[ROWS_QK * EE];

__device__ h16 g_Wq[EE * EE];
__device__ h16 g_Wk[EE * EE];
__device__ h16 g_Wv[EE * EE];
__device__ h16 g_Wo[EE * EE];
__device__ h16 g_W1[128 * 64];
__device__ h16 g_W2[64 * 128];

// ===================== one setup kernel: transposes + zero ================
__global__ void setup_kernel(const float* __restrict__ Wq, const float* __restrict__ Wk,
                             const float* __restrict__ Wv, const float* __restrict__ Wo,
                             const float* __restrict__ W1, const float* __restrict__ W2,
                             h16* __restrict__ oq, h16* __restrict__ ok,
                             h16* __restrict__ ov, h16* __restrict__ oo,
                             h16* __restrict__ o1, h16* __restrict__ o2,
                             float* __restrict__ kv, float* __restrict__ ksum) {
    const int z = blockIdx.z;
    const int tx = threadIdx.x, ty = threadIdx.y;  // 32 x 8
    if (z == 6) {
        int gid = (blockIdx.y * 16 + blockIdx.x) * 256 + ty * 32 + tx;
        for (int i = gid; i < BB * HH * DD * DD; i += 65536) kv[i] = 0.f;
        if (gid < BB * HH * DD) ksum[gid] = 0.f;
        return;
    }
    const float* W;
    h16* o;
    int K, N;
    switch (z) {
        case 0: W = Wq; o = oq; K = 512; N = 512; break;
        case 1: W = Wk; o = ok; K = 512; N = 512; break;
        case 2: W = Wv; o = ov; K = 512; N = 512; break;
        case 3: W = Wo; o = oo; K = 512; N = 512; break;
        case 4: W = W1; o = o1; K = 64;  N = 128; break;
        default: W = W2; o = o2; K = 128; N = 64; break;
    }
    const int n0 = blockIdx.x * 32, k0 = blockIdx.y * 32;
    if (n0 >= N || k0 >= K) return;
    __shared__ float t[32][33];
#pragma unroll
    for (int i = 0; i < 4; i++)
        t[ty + i * 8][tx] = W[(size_t)(k0 + ty + i * 8) * N + n0 + tx];
    __syncthreads();
#pragma unroll
    for (int i = 0; i < 4; i++)
        o[(size_t)(n0 + ty + i * 8) * K + k0 + tx] =
            __float2half(t[tx][ty + i * 8]);
}

// ===================== merged QKV projection GEMM (BK=64, own-thread conv) =
// z=0: q = elu(query@Wq+bq)+1 -> q16 plain
// z=1: kact = elu(key@Wk+bk)+1 -> remapped (CK=64)
// z=2: v = value@Wv+bv -> v16 plain
__global__ void __launch_bounds__(256, 2)
mma_qkv(const float* __restrict__ Aq, const float* __restrict__ Ak,
        const float* __restrict__ Av, const h16* __restrict__ Bq,
        const h16* __restrict__ Bk, const h16* __restrict__ Bv,
        const float* __restrict__ bq, const float* __restrict__ bk,
        const float* __restrict__ bv, h16* __restrict__ q16,
        h16* __restrict__ kact, h16* __restrict__ v16) {
    extern __shared__ char sm[];
    // A32 2x32K @0 ; B 2x16K @65536 ; conv fp16 16K @98304  (112K)
    const int z = blockIdx.z;
    const float* A = (z == 0) ? Aq : (z == 1) ? Ak : Av;
    const h16* B = (z == 0) ? Bq : (z == 1) ? Bk : Bv;
    const float* bias = (z == 0) ? bq : (z == 1) ? bk : bv;

    const int tid = threadIdx.x;
    const int lane = tid & 31, wid = tid >> 5;
    const int wm = wid >> 1, wn = wid & 1;
    const int row0 = blockIdx.y * 128;
    const int col0 = blockIdx.x * 128;
    const uint32_t smb = smem_u32(sm);
    constexpr int K = EE;
    constexpr int nc = K / 64;  // 8

    float acc[2][8][4];
#pragma unroll
    for (int i = 0; i < 2; i++)
#pragma unroll
        for (int j = 0; j < 8; j++)
#pragma unroll
            for (int t = 0; t < 4; t++) acc[i][j][t] = 0.f;

    // loader uses the SAME (r,s) thread map as the converter: thread owning
    // output seg (r,s) loads input segs u=2s and u=2s+1 of row r.
    auto load_stage = [&](int c, int buf) {
        uint32_t as = smb + buf * 32768;
        uint32_t bs = smb + 65536 + buf * 16384;
        const float* Ap = A + (size_t)row0 * K + c * 64;
        const h16* Bp = B + (size_t)col0 * K + c * 64;
#pragma unroll
        for (int j = 0; j < 4; j++) {
            int idx = tid + j * 256;
            int r = idx >> 3, s = idx & 7;
            int u0 = 2 * s, u1 = 2 * s + 1;
            cp_async16(as + (u0 >> 3) * 16384 +
                           SWZ128((uint32_t)(r * 128 + (u0 & 7) * 16)),
                       Ap + (size_t)r * K + u0 * 4);
            cp_async16(as + (u1 >> 3) * 16384 +
                           SWZ128((uint32_t)(r * 128 + (u1 & 7) * 16)),
                       Ap + (size_t)r * K + u1 * 4);
        }
#pragma unroll
        for (int i = 0; i < 4; i++) {
            int idx = tid + i * 256;
            int r = idx >> 3, u = idx & 7;
            cp_async16(bs + SWZ128((uint32_t)(r * 128 + u * 16)),
                       Bp + (size_t)r * K + u * 8);
        }
    };

    load_stage(0, 0);
    CP_COMMIT();

    for (int c = 0; c < nc; c++) {
        if (c + 1 < nc) {
            load_stage(c + 1, (c + 1) & 1);
            CP_COMMIT();
            CP_WAIT1();
        } else {
            CP_WAIT0();
        }
        // own-thread conversion (same (r,s) map as loader): no barrier needed
        {
            char* ap = sm + (c & 1) * 32768;
            char* cvp = sm + 98304;
#pragma unroll
            for (int j = 0; j < 4; j++) {
                int idx = tid + j * 256;
                int r = idx >> 3, s = idx & 7;
                int u0 = 2 * s, u1 = 2 * s + 1;
                float4 a0 = *(const float4*)(ap + (u0 >> 3) * 16384 +
                                             SWZ128((uint32_t)(r * 128 + (u0 & 7) * 16)));
                float4 a1 = *(const float4*)(ap + (u1 >> 3) * 16384 +
                                             SWZ128((uint32_t)(r * 128 + (u1 & 7) * 16)));
                h162 p0, p1, p2, p3;
                p0.x = __float2half(a0.x); p0.y = __float2half(a0.y);
                p1.x = __float2half(a0.z); p1.y = __float2half(a0.w);
                p2.x = __float2half(a1.x); p2.y = __float2half(a1.y);
                p3.x = __float2half(a1.z); p3.y = __float2half(a1.w);
                uint4 pk;
                pk.x = *reinterpret_cast<uint32_t*>(&p0);
                pk.y = *reinterpret_cast<uint32_t*>(&p1);
                pk.z = *reinterpret_cast<uint32_t*>(&p2);
                pk.w = *reinterpret_cast<uint32_t*>(&p3);
                *(uint4*)(cvp + SWZ128((uint32_t)(r * 128 + s * 16))) = pk;
            }
        }
        __syncthreads();
        const uint32_t cvb = smb + 98304;
        const uint32_t bsb = smb + 65536 + (c & 1) * 16384;
#pragma unroll
        for (int ks = 0; ks < 4; ks++) {
            uint32_t ah[2][4], bb[8][2];
#pragma unroll
            for (int mt = 0; mt < 2; mt++) {
                int row = wm * 32 + mt * 16 + (lane & 15);
                int kb = ks * 32 + ((lane >> 4) << 4);
                ldmatrix_x4(cvb + SWZ128((uint32_t)(row * 128 + kb)),
                            ah[mt][0], ah[mt][1], ah[mt][2], ah[mt][3]);
            }
#pragma unroll
            for (int p = 0; p < 4; p++) {
                int row = wn * 64 + p * 16 + ((lane >> 4) << 3) + (lane & 7);
                int kb = ks * 32 + (((lane & 15) >> 3) << 4);
                ldmatrix_x4(bsb + SWZ128((uint32_t)(row * 128 + kb)),
                            bb[2 * p][0], bb[2 * p][1], bb[2 * p + 1][0],
                            bb[2 * p + 1][1]);
            }
#pragma unroll
            for (int mt = 0; mt < 2; mt++)
#pragma unroll
                for (int nt = 0; nt < 8; nt++) mma16816(acc[mt][nt], ah[mt], bb[nt]);
        }
        __syncthreads();
    }

#pragma unroll
    for (int mt = 0; mt < 2; mt++) {
#pragma unroll
        for (int nt = 0; nt < 8; nt++) {
            int col = col0 + wn * 64 + nt * 8 + 2 * (lane & 3);
            float bia0 = bias[col], bia1 = bias[col + 1];
#pragma unroll
            for (int half = 0; half < 2; half++) {
                int row = row0 + wm * 32 + mt * 16 + (lane >> 2) + half * 8;
                float v0 = acc[mt][nt][half * 2 + 0] + bia0;
                float v1 = acc[mt][nt][half * 2 + 1] + bia1;
                if (z != 2) {
                    v0 = (v0 > 0.f) ? (v0 + 1.f) : expf(v0);
                    v1 = (v1 > 0.f) ? (v1 + 1.f) : expf(v1);
                }
                h162 ph; ph.x = __float2half(v0); ph.y = __float2half(v1);
                if (z == 1) {
                    int rp = row * (EE / 64) + col / 64;
                    int cp = col % 64;
                    *(h162*)&kact[(size_t)rp * 64 + cp] = ph;
                } else {
                    h16* dst = (z == 0) ? q16 : v16;
                    *(h162*)&dst[(size_t)row * EE + col] = ph;
                }
            }
        }
    }
}

// ===================== fp16 HMMA GEMM (attn @ Wo -> fp32 out) ==============
__global__ void __launch_bounds__(256, 2)
mma_gemmH(const h16* __restrict__ A, const h16* __restrict__ B,
          const float* __restrict__ bias, float* __restrict__ Cf, int Ntot,
          int K) {
    extern __shared__ char sm[];
    constexpr int STAGE = 2 * 16384;
    const int tid = threadIdx.x;
    const int lane = tid & 31, wid = tid >> 5;
    const int wm = wid >> 1, wn = wid & 1;
    const int row0 = blockIdx.y * 128;
    const int col0 = blockIdx.x * 128;
    const uint32_t smb = smem_u32(sm);
    const int nc = K / 64;

    float acc[2][8][4];
#pragma unroll
    for (int i = 0; i < 2; i++)
#pragma unroll
        for (int j = 0; j < 8; j++)
#pragma unroll
            for (int t = 0; t < 4; t++) acc[i][j][t] = 0.f;

    auto load_stage = [&](int c, int buf) {
        uint32_t as = smb + buf * STAGE;
        uint32_t bs = as + 16384;
        const h16* Ap = A + (size_t)row0 * K + c * 64;
        const h16* Bp = B + (size_t)col0 * K + c * 64;
#pragma unroll
        for (int i = 0; i < 4; i++) {
            int idx = tid + i * 256;
            int r = idx >> 3, u = idx & 7;
            uint32_t so = SWZ128((uint32_t)(r * 128 + u * 16));
            cp_async16(as + so, Ap + (size_t)r * K + u * 8);
            cp_async16(bs + so, Bp + (size_t)r * K + u * 8);
        }
    };

    load_stage(0, 0);
    CP_COMMIT();

    for (int c = 0; c < nc; c++) {
        if (c + 1 < nc) {
            load_stage(c + 1, (c + 1) & 1);
            CP_COMMIT();
            CP_WAIT1();
        } else {
            CP_WAIT0();
        }
        __syncthreads();
        uint32_t as = smb + (c & 1) * STAGE;
        uint32_t bs = as + 16384;
#pragma unroll
        for (int ks = 0; ks < 4; ks++) {
            uint32_t ah[2][4], bb[8][2];
#pragma unroll
            for (int mt = 0; mt < 2; mt++) {
                int row = wm * 32 + mt * 16 + (lane & 15);
                int kb = ks * 32 + ((lane >> 4) << 4);
                ldmatrix_x4(as + SWZ128((uint32_t)(row * 128 + kb)),
                            ah[mt][0], ah[mt][1], ah[mt][2], ah[mt][3]);
            }
#pragma unroll
            for (int p = 0; p < 4; p++) {
                int row = wn * 64 + p * 16 + ((lane >> 4) << 3) + (lane & 7);
                int kb = ks * 32 + (((lane & 15) >> 3) << 4);
                ldmatrix_x4(bs + SWZ128((uint32_t)(row * 128 + kb)),
                            bb[2 * p][0], bb[2 * p][1], bb[2 * p + 1][0],
                            bb[2 * p + 1][1]);
            }
#pragma unroll
            for (int mt = 0; mt < 2; mt++)
#pragma unroll
                for (int nt = 0; nt < 8; nt++) mma16816(acc[mt][nt], ah[mt], bb[nt]);
        }
        __syncthreads();
    }

#pragma unroll
    for (int mt = 0; mt < 2; mt++) {
#pragma unroll
        for (int nt = 0; nt < 8; nt++) {
            int col = col0 + wn * 64 + nt * 8 + 2 * (lane & 3);
            float bia0 = bias[col], bia1 = bias[col + 1];
#pragma unroll
            for (int half = 0; half < 2; half++) {
                int row = row0 + wm * 32 + mt * 16 + (lane >> 2) + half * 8;
                float v0 = acc[mt][nt][half * 2 + 0] + bia0;
                float v1 = acc[mt][nt][half * 2 + 1] + bia1;
                float2 o = make_float2(v0, v1);
                *(float2*)&Cf[(size_t)row * Ntot + col] = o;
            }
        }
    }
}

// ===================== fused per-head key MLP (128-row tiles) ==============
__global__ void __launch_bounds__(256, 2)
mlp_fused(const h16* __restrict__ kin, const h16* __restrict__ W1,
          const h16* __restrict__ W2, const float* __restrict__ b1,
          const float* __restrict__ b2, h16* __restrict__ ka) {
    extern __shared__ char sm[];
    const int tid = threadIdx.x;
    const int lane = tid & 31, wid = tid >> 5;
    const int wm = wid >> 2, wn4 = wid & 3;
    const int row0 = blockIdx.x * 128;
    const uint32_t smb = smem_u32(sm);

#pragma unroll
    for (int i = 0; i < 4; i++) {
        int idx = tid + i * 256;
        int r = idx >> 3, u = idx & 7;
        uint32_t so = SWZ128((uint32_t)(r * 128 + u * 16));
        cp_async16(smb + so, kin + (size_t)(row0 + r) * 64 + u * 8);
        cp_async16(smb + 16384 + so, W1 + r * 64 + u * 8);
    }
#pragma unroll
    for (int i = 0; i < 4; i++) {
        int idx = tid + i * 256;
        int n = idx >> 4, u = idx & 15;
        int khf = u >> 3, u2 = u & 7;
        cp_async16(smb + 65536 + khf * 8192 + SWZ128((uint32_t)(n * 128 + u2 * 16)),
                   W2 + n * 128 + u * 8);
    }
    CP_COMMIT();
    CP_WAIT0();
    __syncthreads();

    float acc1[4][4][4];
#pragma unroll
    for (int i = 0; i < 4; i++)
#pragma unroll
        for (int j = 0; j < 4; j++)
#pragma unroll
            for (int t = 0; t < 4; t++) acc1[i][j][t] = 0.f;

#pragma unroll
    for (int ks = 0; ks < 4; ks++) {
        uint32_t ah[4][4], bb[4][2];
#pragma unroll
        for (int mt = 0; mt < 4; mt++) {
            int row = wm * 64 + mt * 16 + (lane & 15);
            int kb = ks * 32 + ((lane >> 4) << 4);
            ldmatrix_x4(smb + SWZ128((uint32_t)(row * 128 + kb)),
                        ah[mt][0], ah[mt][1], ah[mt][2], ah[mt][3]);
        }
#pragma unroll
        for (int p = 0; p < 2; p++) {
            int row = wn4 * 32 + p * 16 + ((lane >> 4) << 3) + (lane & 7);
            int kb = ks * 32 + (((lane & 15) >> 3) << 4);
            ldmatrix_x4(smb + 16384 + SWZ128((uint32_t)(row * 128 + kb)),
                        bb[2 * p][0], bb[2 * p][1], bb[2 * p + 1][0],
                        bb[2 * p + 1][1]);
        }
#pragma unroll
        for (int mt = 0; mt < 4; mt++)
#pragma unroll
            for (int nt = 0; nt < 4; nt++) mma16816(acc1[mt][nt], ah[mt], bb[nt]);
    }

#pragma unroll
    for (int mt = 0; mt < 4; mt++) {
#pragma unroll
        for (int nt = 0; nt < 4; nt++) {
            int col = wn4 * 32 + nt * 8 + 2 * (lane & 3);
            float bia0 = b1[col], bia1 = b1[col + 1];
            int khf = col >> 6, cc = col & 63;
#pragma unroll
            for (int half = 0; half < 2; half++) {
                int row = wm * 64 + mt * 16 + (lane >> 2) + half * 8;
                float v0 = acc1[mt][nt][half * 2 + 0] + bia0;
                float v1 = acc1[mt][nt][half * 2 + 1] + bia1;
                v0 = 0.5f * v0 * (1.f + erff(v0 * 0.70710678118654752f));
                v1 = 0.5f * v1 * (1.f + erff(v1 * 0.70710678118654752f));
                h162 ph; ph.x = __float2half(v0); ph.y = __float2half(v1);
                *(h162*)(sm + 32768 + khf * 16384 +
                         SWZ128((uint32_t)(row * 128 + cc * 2))) = ph;
            }
        }
    }
    __syncthreads();

    float acc2[4][2][4];
#pragma unroll
    for (int i = 0; i < 4; i++)
#pragma unroll
        for (int j = 0; j < 2; j++)
#pragma unroll
            for (int t = 0; t < 4; t++) acc2[i][j][t] = 0.f;

#pragma unroll
    for (int kstep = 0; kstep < 8; kstep++) {
        int khf = kstep >> 2, ks2 = kstep & 3;
        uint32_t ah[4][4], bb[2][2];
#pragma unroll
        for (int mt = 0; mt < 4; mt++) {
            int row = wm * 64 + mt * 16 + (lane & 15);
            int kb = ks2 * 32 + ((lane >> 4) << 4);
            ldmatrix_x4(smb + 32768 + khf * 16384 +
                            SWZ128((uint32_t)(row * 128 + kb)),
                        ah[mt][0], ah[mt][1], ah[mt][2], ah[mt][3]);
        }
        {
            int row = wn4 * 16 + ((lane >> 4) << 3) + (lane & 7);
            int kb = ks2 * 32 + (((lane & 15) >> 3) << 4);
            ldmatrix_x4(smb + 65536 + khf * 8192 +
                            SWZ128((uint32_t)(row * 128 + kb)),
                        bb[0][0], bb[0][1], bb[1][0], bb[1][1]);
        }
#pragma unroll
        for (int mt = 0; mt < 4; mt++)
#pragma unroll
            for (int nt = 0; nt < 2; nt++) mma16816(acc2[mt][nt], ah[mt], bb[nt]);
    }

#pragma unroll
    for (int mt = 0; mt < 4; mt++) {
#pragma unroll
        for (int nt = 0; nt < 2; nt++) {
            int col = wn4 * 16 + nt * 8 + 2 * (lane & 3);
            float bia0 = b2[col], bia1 = b2[col + 1];
#pragma unroll
            for (int half = 0; half < 2; half++) {
                int row = wm * 64 + mt * 16 + (lane >> 2) + half * 8;
                float v0 = acc2[mt][nt][half * 2 + 0] + bia0;
                float v1 = acc2[mt][nt][half * 2 + 1] + bia1;
                v0 = (v0 > 0.f) ? (v0 + 1.f) : expf(v0);
                v1 = (v1 > 0.f) ? (v1 + 1.f) : expf(v1);
                h162 ph; ph.x = __float2half(v0); ph.y = __float2half(v1);
                *(h162*)&ka[(size_t)(row0 + row) * 64 + col] = ph;
            }
        }
    }
}

// ===================== kv context via tensor cores =========================
__global__ void __launch_bounds__(256, 4)
kv_tc(const h16* __restrict__ ka, const h16* __restrict__ v,
      float* __restrict__ kv, float* __restrict__ ksum) {
    extern __shared__ char sm[];
    const int bh = blockIdx.x;
    const int b = bh / HH, h = bh % HH;
    const int m0 = blockIdx.y * 256;
    const int tid = threadIdx.x;
    const int lane = tid & 31, wid = tid >> 5;
    const int wd = wid >> 1, we = wid & 1;
    const uint32_t smb = smem_u32(sm);

    float acc[4][4];
    float aks[4] = {0.f, 0.f, 0.f, 0.f};
#pragma unroll
    for (int i = 0; i < 4; i++)
#pragma unroll
        for (int j = 0; j < 4; j++) acc[i][j] = 0.f;

    const size_t vbase = (size_t)b * MMCTX * EE + (size_t)h * DD;
    const size_t kabase = ((size_t)b * MMCTX) * HH + h;

    auto load_tile = [&](int t, int buf) {
        const int m = m0 + t * 32;
        int r = tid >> 3, u = tid & 7;
        uint32_t off = SWZ128((uint32_t)(r * 128 + u * 16));
        cp_async16(smb + buf * 4096 + off,
                   ka + (kabase + (size_t)(m + r) * HH) * 64 + u * 8);
        cp_async16(smb + 8192 + buf * 4096 + off,
                   v + vbase + (size_t)(m + r) * EE + u * 8);
    };

    load_tile(0, 0);
    CP_COMMIT();

    const uint32_t ones[2] = {0x3C003C00u, 0x3C003C00u};

    for (int t = 0; t < 8; t++) {
        if (t + 1 < 8) {
            load_tile(t + 1, (t + 1) & 1);
            CP_COMMIT();
            CP_WAIT1();
        } else {
            CP_WAIT0();
        }
        __syncthreads();
        const uint32_t kas = smb + (t & 1) * 4096;
        const uint32_t vs = smb + 8192 + (t & 1) * 4096;
#pragma unroll
        for (int ks2 = 0; ks2 < 2; ks2++) {
            const int mb = ks2 * 16;
            uint32_t a[4];
            {
                int row = mb + ((lane >> 4) << 3) + (lane & 7);
                int cb = wd * 32 + (((lane >> 3) & 1) << 4);
                ldmatrix_x4t(kas + SWZ128((uint32_t)(row * 128 + cb)),
                             a[0], a[1], a[2], a[3]);
            }
            uint32_t bb[4][2];
#pragma unroll
            for (int p = 0; p < 2; p++) {
                int row = mb + (((lane >> 3) & 1) << 3) + (lane & 7);
                int cb = we * 64 + p * 32 + ((lane >> 4) << 4);
                uint32_t r0, r1, r2, r3;
                ldmatrix_x4t(vs + SWZ128((uint32_t)(row * 128 + cb)),
                             r0, r1, r2, r3);
                bb[2 * p][0] = r0; bb[2 * p][1] = r1;
                bb[2 * p + 1][0] = r2; bb[2 * p + 1][1] = r3;
            }
#pragma unroll
            for (int nt = 0; nt < 4; nt++) mma16816(acc[nt], a, bb[nt]);
            if (we == 0) mma16816(aks, a, ones);
        }
        __syncthreads();
    }

    const float inv_m = 1.f / (float)MMCTX;
    const int r0 = wd * 16 + (lane >> 2);
    float* kvb = kv + (size_t)bh * DD * DD;
#pragma unroll
    for (int nt = 0; nt < 4; nt++) {
        int col = we * 32 + nt * 8 + (lane & 3) * 2;
        atomicAdd(&kvb[r0 * DD + col], acc[nt][0] * inv_m);
        atomicAdd(&kvb[r0 * DD + col + 1], acc[nt][1] * inv_m);
        atomicAdd(&kvb[(r0 + 8) * DD + col], acc[nt][2] * inv_m);
        atomicAdd(&kvb[(r0 + 8) * DD + col + 1], acc[nt][3] * inv_m);
    }
    if (we == 0 && (lane & 3) == 0) {
        atomicAdd(&ksum[bh * DD + r0], aks[0] * inv_m);
        atomicAdd(&ksum[bh * DD + r0 + 8], aks[2] * inv_m);
    }
}

// ===================== out einsum via tensor cores =========================
__global__ void __launch_bounds__(256, 2)
out_tc(const h16* __restrict__ q, const float* __restrict__ kv,
       const float* __restrict__ ksum, h16* __restrict__ attn) {
    extern __shared__ char sm[];
    // qA 16K @0 ; Bkv fp16 8K @16384 ; kvs fp32 [64][68] @24576 (17408) ;
    // kss fp32 @41984 (256) ; den fp32 @42240 (512)  => 42752
    const int bh = blockIdx.x;
    const int b = bh / HH, h = bh % HH;
    const int n0 = blockIdx.y * 128;
    const int tid = threadIdx.x;
    const int lane = tid & 31, wid = tid >> 5;
    const int wm = wid >> 1, wn = wid & 1;
    const uint32_t smb = smem_u32(sm);
    float* kvs = (float*)(sm + 24576);
    float* kss = (float*)(sm + 41984);
    float* den = (float*)(sm + 42240);

    const size_t qbase = ((size_t)b * NN + n0) * EE + (size_t)h * DD;
#pragma unroll
    for (int i = 0; i < 4; i++) {
        int idx = tid + i * 256;
        int r = idx >> 3, u = idx & 7;
        cp_async16(smb + SWZ128((uint32_t)(r * 128 + u * 16)),
                   q + qbase + (size_t)r * EE + u * 8);
    }
    {
        const float* kvg = kv + (size_t)bh * DD * DD;
#pragma unroll
        for (int i = 0; i < 4; i++) {
            int j = (tid + i * 256) * 4;
            int d = j >> 6, e = j & 63;
            float4 val = *(const float4*)&kvg[j];
            *(float4*)&kvs[d * 68 + e] = val;
        }
    }
    if (tid < 16) {
        float4 val = *(const float4*)&ksum[bh * DD + tid * 4];
        *(float4*)&kss[tid * 4] = val;
    }
    CP_COMMIT();
    CP_WAIT0();
    __syncthreads();

    {
        int e = tid >> 2, db = (tid & 3) * 16;
#pragma unroll
        for (int dd2 = 0; dd2 < 16; dd2 += 2) {
            int d = db + dd2;
            h162 ph;
            ph.x = __float2half(kvs[d * 68 + e]);
            ph.y = __float2half(kvs[(d + 1) * 68 + e]);
            *(h162*)(sm + 16384 + SWZ128((uint32_t)(e * 128 + d * 2))) = ph;
        }
    }
    if (tid < 128) {
        float s = 0.f;
#pragma unroll
        for (int u = 0; u < 8; u++) {
            uint4 raw = *(const uint4*)(sm + SWZ128((uint32_t)(tid * 128 + u * 16)));
            const h162* hp = (const h162*)&raw;
#pragma unroll
            for (int j = 0; j < 4; j++) {
                float2 f = __half22float2(hp[j]);
                s += f.x * kss[u * 8 + j * 2] + f.y * kss[u * 8 + j * 2 + 1];
            }
        }
        den[tid] = fmaxf(s, 1e-6f);
    }
    __syncthreads();

    float acc[2][4][4];
#pragma unroll
    for (int i = 0; i < 2; i++)
#pragma unroll
        for (int j = 0; j < 4; j++)
#pragma unroll
            for (int t = 0; t < 4; t++) acc[i][j][t] = 0.f;

#pragma unroll
    for (int ks2 = 0; ks2 < 4; ks2++) {
        uint32_t ah[2][4], bb[4][2];
#pragma unroll
        for (int mt = 0; mt < 2; mt++) {
            int row = wm * 32 + mt * 16 + (lane & 15);
            int kb = ks2 * 32 + ((lane >> 4) << 4);
            ldmatrix_x4(smb + SWZ128((uint32_t)(row * 128 + kb)),
                        ah[mt][0], ah[mt][1], ah[mt][2], ah[mt][3]);
        }
#pragma unroll
        for (int p = 0; p < 2; p++) {
            int row = wn * 32 + p * 16 + ((lane >> 4) << 3) + (lane & 7);
            int kb = ks2 * 32 + (((lane & 15) >> 3) << 4);
            uint32_t r0, r1, r2, r3;
            ldmatrix_x4(smb + 16384 + SWZ128((uint32_t)(row * 128 + kb)),
                        r0, r1, r2, r3);
            bb[2 * p][0] = r0; bb[2 * p][1] = r1;
            bb[2 * p + 1][0] = r2; bb[2 * p + 1][1] = r3;
        }
#pragma unroll
        for (int mt = 0; mt < 2; mt++)
#pragma unroll
            for (int nt = 0; nt < 4; nt++) mma16816(acc[mt][nt], ah[mt], bb[nt]);
    }

#pragma unroll
    for (int mt = 0; mt < 2; mt++) {
#pragma unroll
        for (int nt = 0; nt < 4; nt++) {
            int col = wn * 32 + nt * 8 + (lane & 3) * 2;
#pragma unroll
            for (int half = 0; half < 2; half++) {
                int row = wm * 32 + mt * 16 + (lane >> 2) + half * 8;
                float rcp = 1.f / den[row];
                float v0 = acc[mt][nt][half * 2 + 0] * rcp;
                float v1 = acc[mt][nt][half * 2 + 1] * rcp;
                v0 = isnan(v0) ? 0.f : fminf(fmaxf(v0, -65000.f), 65000.f);
                v1 = isnan(v1) ? 0.f : fminf(fmaxf(v1, -65000.f), 65000.f);
                h162 ph; ph.x = __float2half(v0); ph.y = __float2half(v1);
                *(h162*)&attn[qbase + (size_t)row * EE + col] = ph;
            }
        }
    }
}

// ===================== launch =====================
extern "C" void kernel_launch(void* const* d_in, const int* in_sizes, int n_in,
                              void* d_out, int out_size) {
    const float* query = (const float*)d_in[0];
    const float* key   = (const float*)d_in[1];
    const float* value = (const float*)d_in[2];
    const float* Wq = (const float*)d_in[3];
    const float* bq = (const float*)d_in[4];
    const float* Wk = (const float*)d_in[5];
    const float* bk = (const float*)d_in[6];
    const float* Wv = (const float*)d_in[7];
    const float* bv = (const float*)d_in[8];
    const float* W1 = (const float*)d_in[9];
    const float* b1 = (const float*)d_in[10];
    const float* W2 = (const float*)d_in[11];
    const float* b2 = (const float*)d_in[12];
    const float* Wo = (const float*)d_in[13];
    const float* bo = (const float*)d_in[14];
    float* out = (float*)d_out;

    float *kv_s, *ksum_s;
    cudaGetSymbolAddress((void**)&kv_s, g_kv);
    cudaGetSymbolAddress((void**)&ksum_s, g_ksum);

    h16 *q16, *v16, *ka16, *kact, *attn, *Wqd, *Wkd, *Wvd, *Wod, *W1d, *W2d;
    cudaGetSymbolAddress((void**)&q16, g_q16);
    cudaGetSymbolAddress((void**)&v16, g_v16);
    cudaGetSymbolAddress((void**)&ka16, g_ka16);
    cudaGetSymbolAddress((void**)&kact, g_kact);
    cudaGetSymbolAddress((void**)&attn, g_attn);
    cudaGetSymbolAddress((void**)&Wqd, g_Wq);
    cudaGetSymbolAddress((void**)&Wkd, g_Wk);
    cudaGetSymbolAddress((void**)&Wvd, g_Wv);
    cudaGetSymbolAddress((void**)&Wod, g_Wo);
    cudaGetSymbolAddress((void**)&W1d, g_W1);
    cudaGetSymbolAddress((void**)&W2d, g_W2);

    const int SMQKV = 114688;
    const int SMH = 65536;
    const int SMM = 81920;
    const int SMKV = 16384;
    const int SMOUT = 42752;
    cudaFuncSetAttribute((const void*)mma_qkv,
                         cudaFuncAttributeMaxDynamicSharedMemorySize, SMQKV);
    cudaFuncSetAttribute((const void*)mma_gemmH,
                         cudaFuncAttributeMaxDynamicSharedMemorySize, SMH);
    cudaFuncSetAttribute((const void*)mlp_fused,
                         cudaFuncAttributeMaxDynamicSharedMemorySize, SMM);
    cudaFuncSetAttribute((const void*)kv_tc,
                         cudaFuncAttributeMaxDynamicSharedMemorySize, SMKV);
    cudaFuncSetAttribute((const void*)out_tc,
                         cudaFuncAttributeMaxDynamicSharedMemorySize, SMOUT);

    // ---- setup: all weight transposes + zero in one launch
    {
        dim3 blk(32, 8);
        setup_kernel<<<dim3(16, 16, 7), blk>>>(Wq, Wk, Wv, Wo, W1, W2,
                                               Wqd, Wkd, Wvd, Wod, W1d, W2d,
                                               kv_s, ksum_s);
    }
    // ---- merged Q/K/V projections (BK=64, own-thread conversion)
    {
        dim3 grid(EE / 128, ROWS_QK / 128, 3);
        mma_qkv<<<grid, 256, SMQKV>>>(query, key, value, Wqd, Wkd, Wvd,
                                      bq, bk, bv, q16, kact, v16);
    }
    // ---- fused key MLP
    mlp_fused<<<ROWS_MLP / 128, 256, SMM>>>(kact, W1d, W2d, b1, b2, ka16);
    // ---- kv context + ksum via tensor cores
    {
        dim3 gkv(BB * HH, MMCTX / 256);
        kv_tc<<<gkv, 256, SMKV>>>(ka16, v16, kv_s, ksum_s);
    }
    // ---- out einsum + normalize via tensor cores
    {
        dim3 go(BB * HH, NN / 128);
        out_tc<<<go, 256, SMOUT>>>(q16, kv_s, ksum_s, attn);
    }
    // ---- final projection
    {
        dim3 grid(EE / 128, ROWS_QK / 128);
        mma_gemmH<<<grid, 256, SMH>>>(attn, Wod, bo, out, EE, EE);
    }
}

// round 16
// speedup vs baseline: 1.1126x; 1.1126x over previous
#include <cuda_runtime.h>
#include <cuda_fp16.h>
#include <math.h>
#include <stdint.h>

#define BB 4
#define NN 4096
#define MMCTX 4096
#define EE 512
#define HH 8
#define DD 64
#define ROWS_QK (BB * NN)          // 16384
#define ROWS_MLP (BB * MMCTX * HH) // 131072

typedef __half h16;
typedef __half2 h162;

__device__ __forceinline__ uint32_t smem_u32(const void* p) {
    uint32_t a;
    asm("{ .reg .u64 t; cvta.to.shared.u64 t, %1; cvt.u32.u64 %0, t; }"
        : "=r"(a) : "l"(p));
    return a;
}

#define SWZ128(b) ((b) ^ (((b) >> 3) & 0x70))

__device__ __forceinline__ void cp_async16(uint32_t dst, const void* src) {
    asm volatile("cp.async.cg.shared.global [%0], [%1], 16;\n"
                 :: "r"(dst), "l"(src));
}
#define CP_COMMIT() asm volatile("cp.async.commit_group;\n" ::: "memory")
#define CP_WAIT1() asm volatile("cp.async.wait_group 1;\n" ::: "memory")
#define CP_WAIT0() asm volatile("cp.async.wait_group 0;\n" ::: "memory")

__device__ __forceinline__ void ldmatrix_x4(uint32_t addr, uint32_t& r0,
                                            uint32_t& r1, uint32_t& r2,
                                            uint32_t& r3) {
    asm volatile("ldmatrix.sync.aligned.m8n8.x4.shared.b16 {%0,%1,%2,%3}, [%4];"
                 : "=r"(r0), "=r"(r1), "=r"(r2), "=r"(r3) : "r"(addr));
}

__device__ __forceinline__ void ldmatrix_x4t(uint32_t addr, uint32_t& r0,
                                             uint32_t& r1, uint32_t& r2,
                                             uint32_t& r3) {
    asm volatile(
        "ldmatrix.sync.aligned.m8n8.x4.trans.shared.b16 {%0,%1,%2,%3}, [%4];"
        : "=r"(r0), "=r"(r1), "=r"(r2), "=r"(r3) : "r"(addr));
}

__device__ __forceinline__ void mma16816(float* c, const uint32_t* a,
                                         const uint32_t* b) {
    asm volatile(
        "mma.sync.aligned.m16n8k16.row.col.f32.f16.f16.f32 "
        "{%0,%1,%2,%3}, {%4,%5,%6,%7}, {%8,%9}, {%0,%1,%2,%3};"
        : "+f"(c[0]), "+f"(c[1]), "+f"(c[2]), "+f"(c[3])
        : "r"(a[0]), "r"(a[1]), "r"(a[2]), "r"(a[3]), "r"(b[0]), "r"(b[1]));
}

// ===================== scratch =====================
__device__ h16 g_q16[ROWS_QK * EE];
__device__ h16 g_v16[ROWS_QK * EE];
__device__ h16 g_ka16[ROWS_MLP * DD];
__device__ float g_kv[BB * HH * DD * DD];
__device__ float g_ksum[BB * HH * DD];

__device__ h16 g_kact[ROWS_MLP * DD];
__device__ h16 g_attn[ROWS_QK * EE];

__device__ h16 g_Wq[EE * EE];
__device__ h16 g_Wk[EE * EE];
__device__ h16 g_Wv[EE * EE];
__device__ h16 g_Wo[EE * EE];
__device__ h16 g_W1[128 * 64];
__device__ h16 g_W2[64 * 128];

// ===================== one setup kernel: transposes + zero ================
__global__ void setup_kernel(const float* __restrict__ Wq, const float* __restrict__ Wk,
                             const float* __restrict__ Wv, const float* __restrict__ Wo,
                             const float* __restrict__ W1, const float* __restrict__ W2,
                             h16* __restrict__ oq, h16* __restrict__ ok,
                             h16* __restrict__ ov, h16* __restrict__ oo,
                             h16* __restrict__ o1, h16* __restrict__ o2,
                             float* __restrict__ kv, float* __restrict__ ksum) {
    const int z = blockIdx.z;
    const int tx = threadIdx.x, ty = threadIdx.y;  // 32 x 8
    if (z == 6) {
        int gid = (blockIdx.y * 16 + blockIdx.x) * 256 + ty * 32 + tx;
        for (int i = gid; i < BB * HH * DD * DD; i += 65536) kv[i] = 0.f;
        if (gid < BB * HH * DD) ksum[gid] = 0.f;
        return;
    }
    const float* W;
    h16* o;
    int K, N;
    switch (z) {
        case 0: W = Wq; o = oq; K = 512; N = 512; break;
        case 1: W = Wk; o = ok; K = 512; N = 512; break;
        case 2: W = Wv; o = ov; K = 512; N = 512; break;
        case 3: W = Wo; o = oo; K = 512; N = 512; break;
        case 4: W = W1; o = o1; K = 64;  N = 128; break;
        default: W = W2; o = o2; K = 128; N = 64; break;
    }
    const int n0 = blockIdx.x * 32, k0 = blockIdx.y * 32;
    if (n0 >= N || k0 >= K) return;
    __shared__ float t[32][33];
#pragma unroll
    for (int i = 0; i < 4; i++)
        t[ty + i * 8][tx] = W[(size_t)(k0 + ty + i * 8) * N + n0 + tx];
    __syncthreads();
#pragma unroll
    for (int i = 0; i < 4; i++)
        o[(size_t)(n0 + ty + i * 8) * K + k0 + tx] =
            __float2half(t[tx][ty + i * 8]);
}

// ===================== merged QKV projection GEMM (BK=32, own-thread conv) =
// z=0: q = elu(query@Wq+bq)+1 -> q16 plain
// z=1: kact = elu(key@Wk+bk)+1 -> remapped (CK=64)
// z=2: v = value@Wv+bv -> v16 plain
__global__ void __launch_bounds__(256, 2)
mma_qkv(const float* __restrict__ Aq, const float* __restrict__ Ak,
        const float* __restrict__ Av, const h16* __restrict__ Bq,
        const h16* __restrict__ Bk, const h16* __restrict__ Bv,
        const float* __restrict__ bq, const float* __restrict__ bk,
        const float* __restrict__ bv, h16* __restrict__ q16,
        h16* __restrict__ kact, h16* __restrict__ v16) {
    extern __shared__ char sm[];
    // A32 2x16K @0 ; B 2x16K @32768 ; conv fp16 16K @65536   (80K)
    const int z = blockIdx.z;
    const float* A = (z == 0) ? Aq : (z == 1) ? Ak : Av;
    const h16* B = (z == 0) ? Bq : (z == 1) ? Bk : Bv;
    const float* bias = (z == 0) ? bq : (z == 1) ? bk : bv;

    const int tid = threadIdx.x;
    const int lane = tid & 31, wid = tid >> 5;
    const int wm = wid >> 1, wn = wid & 1;
    const int row0 = blockIdx.y * 128;
    const int col0 = blockIdx.x * 128;
    const uint32_t smb = smem_u32(sm);
    constexpr int K = EE;
    constexpr int nc = K / 32;  // 16

    float acc[2][8][4];
#pragma unroll
    for (int i = 0; i < 2; i++)
#pragma unroll
        for (int j = 0; j < 8; j++)
#pragma unroll
            for (int t = 0; t < 4; t++) acc[i][j][t] = 0.f;

    auto load_stage = [&](int c, int buf) {
        uint32_t as = smb + buf * 16384;
        uint32_t bs = smb + 32768 + buf * 16384;
        const float* Ap = A + (size_t)row0 * K + c * 32;
        const h16* Bp = B + (size_t)col0 * K + c * 32;
#pragma unroll
        for (int i = 0; i < 4; i++) {
            int idx = tid + i * 256;
            int r = idx >> 3, u = idx & 7;
            cp_async16(as + SWZ128((uint32_t)(r * 128 + u * 16)),
                       Ap + (size_t)r * K + u * 4);
        }
#pragma unroll
        for (int i = 0; i < 2; i++) {
            int idx = tid + i * 256;
            int r = idx >> 2, u = idx & 3;
            cp_async16(bs + SWZ128((uint32_t)(r * 128 + u * 16)),
                       Bp + (size_t)r * K + u * 8);
        }
    };

    load_stage(0, 0);
    CP_COMMIT();

    for (int c = 0; c < nc; c++) {
        if (c + 1 < nc) {
            load_stage(c + 1, (c + 1) & 1);
            CP_COMMIT();
            CP_WAIT1();
        } else {
            CP_WAIT0();
        }
        // own-thread conversion: same idx->(r,u) map as loader, no barrier needed
        {
            char* ap = sm + (c & 1) * 16384;
            char* cvp = sm + 65536;
#pragma unroll
            for (int i = 0; i < 4; i++) {
                int idx = tid + i * 256;
                int r = idx >> 3, u = idx & 7;
                float4 v4 = *(const float4*)(ap + SWZ128((uint32_t)(r * 128 + u * 16)));
                h162 p0; p0.x = __float2half(v4.x); p0.y = __float2half(v4.y);
                h162 p1; p1.x = __float2half(v4.z); p1.y = __float2half(v4.w);
                uint32_t d = SWZ128((uint32_t)(r * 128 + u * 8));
                *(h162*)(cvp + d) = p0;
                *(h162*)(cvp + d + 4) = p1;
            }
        }
        __syncthreads();
        const uint32_t cvb = smb + 65536;
        const uint32_t bsb = smb + 32768 + (c & 1) * 16384;
#pragma unroll
        for (int ks = 0; ks < 2; ks++) {
            uint32_t ah[2][4], bb[8][2];
#pragma unroll
            for (int mt = 0; mt < 2; mt++) {
                int row = wm * 32 + mt * 16 + (lane & 15);
                int kb = ks * 32 + ((lane >> 4) << 4);
                ldmatrix_x4(cvb + SWZ128((uint32_t)(row * 128 + kb)),
                            ah[mt][0], ah[mt][1], ah[mt][2], ah[mt][3]);
            }
#pragma unroll
            for (int p = 0; p < 4; p++) {
                int row = wn * 64 + p * 16 + ((lane >> 4) << 3) + (lane & 7);
                int kb = ks * 32 + (((lane & 15) >> 3) << 4);
                ldmatrix_x4(bsb + SWZ128((uint32_t)(row * 128 + kb)),
                            bb[2 * p][0], bb[2 * p][1], bb[2 * p + 1][0],
                            bb[2 * p + 1][1]);
            }
#pragma unroll
            for (int mt = 0; mt < 2; mt++)
#pragma unroll
                for (int nt = 0; nt < 8; nt++) mma16816(acc[mt][nt], ah[mt], bb[nt]);
        }
        __syncthreads();
    }

#pragma unroll
    for (int mt = 0; mt < 2; mt++) {
#pragma unroll
        for (int nt = 0; nt < 8; nt++) {
            int col = col0 + wn * 64 + nt * 8 + 2 * (lane & 3);
            float bia0 = bias[col], bia1 = bias[col + 1];
#pragma unroll
            for (int half = 0; half < 2; half++) {
                int row = row0 + wm * 32 + mt * 16 + (lane >> 2) + half * 8;
                float v0 = acc[mt][nt][half * 2 + 0] + bia0;
                float v1 = acc[mt][nt][half * 2 + 1] + bia1;
                if (z != 2) {
                    v0 = (v0 > 0.f) ? (v0 + 1.f) : expf(v0);
                    v1 = (v1 > 0.f) ? (v1 + 1.f) : expf(v1);
                }
                h162 ph; ph.x = __float2half(v0); ph.y = __float2half(v1);
                if (z == 1) {
                    int rp = row * (EE / 64) + col / 64;
                    int cp = col % 64;
                    *(h162*)&kact[(size_t)rp * 64 + cp] = ph;
                } else {
                    h16* dst = (z == 0) ? q16 : v16;
                    *(h162*)&dst[(size_t)row * EE + col] = ph;
                }
            }
        }
    }
}

// ===================== fp16 HMMA GEMM (attn @ Wo -> fp32 out) ==============
__global__ void __launch_bounds__(256, 2)
mma_gemmH(const h16* __restrict__ A, const h16* __restrict__ B,
          const float* __restrict__ bias, float* __restrict__ Cf, int Ntot,
          int K) {
    extern __shared__ char sm[];
    constexpr int STAGE = 2 * 16384;
    const int tid = threadIdx.x;
    const int lane = tid & 31, wid = tid >> 5;
    const int wm = wid >> 1, wn = wid & 1;
    const int row0 = blockIdx.y * 128;
    const int col0 = blockIdx.x * 128;
    const uint32_t smb = smem_u32(sm);
    const int nc = K / 64;

    float acc[2][8][4];
#pragma unroll
    for (int i = 0; i < 2; i++)
#pragma unroll
        for (int j = 0; j < 8; j++)
#pragma unroll
            for (int t = 0; t < 4; t++) acc[i][j][t] = 0.f;

    auto load_stage = [&](int c, int buf) {
        uint32_t as = smb + buf * STAGE;
        uint32_t bs = as + 16384;
        const h16* Ap = A + (size_t)row0 * K + c * 64;
        const h16* Bp = B + (size_t)col0 * K + c * 64;
#pragma unroll
        for (int i = 0; i < 4; i++) {
            int idx = tid + i * 256;
            int r = idx >> 3, u = idx & 7;
            uint32_t so = SWZ128((uint32_t)(r * 128 + u * 16));
            cp_async16(as + so, Ap + (size_t)r * K + u * 8);
            cp_async16(bs + so, Bp + (size_t)r * K + u * 8);
        }
    };

    load_stage(0, 0);
    CP_COMMIT();

    for (int c = 0; c < nc; c++) {
        if (c + 1 < nc) {
            load_stage(c + 1, (c + 1) & 1);
            CP_COMMIT();
            CP_WAIT1();
        } else {
            CP_WAIT0();
        }
        __syncthreads();
        uint32_t as = smb + (c & 1) * STAGE;
        uint32_t bs = as + 16384;
#pragma unroll
        for (int ks = 0; ks < 4; ks++) {
            uint32_t ah[2][4], bb[8][2];
#pragma unroll
            for (int mt = 0; mt < 2; mt++) {
                int row = wm * 32 + mt * 16 + (lane & 15);
                int kb = ks * 32 + ((lane >> 4) << 4);
                ldmatrix_x4(as + SWZ128((uint32_t)(row * 128 + kb)),
                            ah[mt][0], ah[mt][1], ah[mt][2], ah[mt][3]);
            }
#pragma unroll
            for (int p = 0; p < 4; p++) {
                int row = wn * 64 + p * 16 + ((lane >> 4) << 3) + (lane & 7);
                int kb = ks * 32 + (((lane & 15) >> 3) << 4);
                ldmatrix_x4(bs + SWZ128((uint32_t)(row * 128 + kb)),
                            bb[2 * p][0], bb[2 * p][1], bb[2 * p + 1][0],
                            bb[2 * p + 1][1]);
            }
#pragma unroll
            for (int mt = 0; mt < 2; mt++)
#pragma unroll
                for (int nt = 0; nt < 8; nt++) mma16816(acc[mt][nt], ah[mt], bb[nt]);
        }
        __syncthreads();
    }

#pragma unroll
    for (int mt = 0; mt < 2; mt++) {
#pragma unroll
        for (int nt = 0; nt < 8; nt++) {
            int col = col0 + wn * 64 + nt * 8 + 2 * (lane & 3);
            float bia0 = bias[col], bia1 = bias[col + 1];
#pragma unroll
            for (int half = 0; half < 2; half++) {
                int row = row0 + wm * 32 + mt * 16 + (lane >> 2) + half * 8;
                float v0 = acc[mt][nt][half * 2 + 0] + bia0;
                float v1 = acc[mt][nt][half * 2 + 1] + bia1;
                float2 o = make_float2(v0, v1);
                *(float2*)&Cf[(size_t)row * Ntot + col] = o;
            }
        }
    }
}

// ===================== fused per-head key MLP (128-row tiles) ==============
__global__ void __launch_bounds__(256, 2)
mlp_fused(const h16* __restrict__ kin, const h16* __restrict__ W1,
          const h16* __restrict__ W2, const float* __restrict__ b1,
          const float* __restrict__ b2, h16* __restrict__ ka) {
    extern __shared__ char sm[];
    const int tid = threadIdx.x;
    const int lane = tid & 31, wid = tid >> 5;
    const int wm = wid >> 2, wn4 = wid & 3;
    const int row0 = blockIdx.x * 128;
    const uint32_t smb = smem_u32(sm);

#pragma unroll
    for (int i = 0; i < 4; i++) {
        int idx = tid + i * 256;
        int r = idx >> 3, u = idx & 7;
        uint32_t so = SWZ128((uint32_t)(r * 128 + u * 16));
        cp_async16(smb + so, kin + (size_t)(row0 + r) * 64 + u * 8);
        cp_async16(smb + 16384 + so, W1 + r * 64 + u * 8);
    }
#pragma unroll
    for (int i = 0; i < 4; i++) {
        int idx = tid + i * 256;
        int n = idx >> 4, u = idx & 15;
        int khf = u >> 3, u2 = u & 7;
        cp_async16(smb + 65536 + khf * 8192 + SWZ128((uint32_t)(n * 128 + u2 * 16)),
                   W2 + n * 128 + u * 8);
    }
    CP_COMMIT();
    CP_WAIT0();
    __syncthreads();

    float acc1[4][4][4];
#pragma unroll
    for (int i = 0; i < 4; i++)
#pragma unroll
        for (int j = 0; j < 4; j++)
#pragma unroll
            for (int t = 0; t < 4; t++) acc1[i][j][t] = 0.f;

#pragma unroll
    for (int ks = 0; ks < 4; ks++) {
        uint32_t ah[4][4], bb[4][2];
#pragma unroll
        for (int mt = 0; mt < 4; mt++) {
            int row = wm * 64 + mt * 16 + (lane & 15);
            int kb = ks * 32 + ((lane >> 4) << 4);
            ldmatrix_x4(smb + SWZ128((uint32_t)(row * 128 + kb)),
                        ah[mt][0], ah[mt][1], ah[mt][2], ah[mt][3]);
        }
#pragma unroll
        for (int p = 0; p < 2; p++) {
            int row = wn4 * 32 + p * 16 + ((lane >> 4) << 3) + (lane & 7);
            int kb = ks * 32 + (((lane & 15) >> 3) << 4);
            ldmatrix_x4(smb + 16384 + SWZ128((uint32_t)(row * 128 + kb)),
                        bb[2 * p][0], bb[2 * p][1], bb[2 * p + 1][0],
                        bb[2 * p + 1][1]);
        }
#pragma unroll
        for (int mt = 0; mt < 4; mt++)
#pragma unroll
            for (int nt = 0; nt < 4; nt++) mma16816(acc1[mt][nt], ah[mt], bb[nt]);
    }

#pragma unroll
    for (int mt = 0; mt < 4; mt++) {
#pragma unroll
        for (int nt = 0; nt < 4; nt++) {
            int col = wn4 * 32 + nt * 8 + 2 * (lane & 3);
            float bia0 = b1[col], bia1 = b1[col + 1];
            int khf = col >> 6, cc = col & 63;
#pragma unroll
            for (int half = 0; half < 2; half++) {
                int row = wm * 64 + mt * 16 + (lane >> 2) + half * 8;
                float v0 = acc1[mt][nt][half * 2 + 0] + bia0;
                float v1 = acc1[mt][nt][half * 2 + 1] + bia1;
                v0 = 0.5f * v0 * (1.f + erff(v0 * 0.70710678118654752f));
                v1 = 0.5f * v1 * (1.f + erff(v1 * 0.70710678118654752f));
                h162 ph; ph.x = __float2half(v0); ph.y = __float2half(v1);
                *(h162*)(sm + 32768 + khf * 16384 +
                         SWZ128((uint32_t)(row * 128 + cc * 2))) = ph;
            }
        }
    }
    __syncthreads();

    float acc2[4][2][4];
#pragma unroll
    for (int i = 0; i < 4; i++)
#pragma unroll
        for (int j = 0; j < 2; j++)
#pragma unroll
            for (int t = 0; t < 4; t++) acc2[i][j][t] = 0.f;

#pragma unroll
    for (int kstep = 0; kstep < 8; kstep++) {
        int khf = kstep >> 2, ks2 = kstep & 3;
        uint32_t ah[4][4], bb[2][2];
#pragma unroll
        for (int mt = 0; mt < 4; mt++) {
            int row = wm * 64 + mt * 16 + (lane & 15);
            int kb = ks2 * 32 + ((lane >> 4) << 4);
            ldmatrix_x4(smb + 32768 + khf * 16384 +
                            SWZ128((uint32_t)(row * 128 + kb)),
                        ah[mt][0], ah[mt][1], ah[mt][2], ah[mt][3]);
        }
        {
            int row = wn4 * 16 + ((lane >> 4) << 3) + (lane & 7);
            int kb = ks2 * 32 + (((lane & 15) >> 3) << 4);
            ldmatrix_x4(smb + 65536 + khf * 8192 +
                            SWZ128((uint32_t)(row * 128 + kb)),
                        bb[0][0], bb[0][1], bb[1][0], bb[1][1]);
        }
#pragma unroll
        for (int mt = 0; mt < 4; mt++)
#pragma unroll
            for (int nt = 0; nt < 2; nt++) mma16816(acc2[mt][nt], ah[mt], bb[nt]);
    }

#pragma unroll
    for (int mt = 0; mt < 4; mt++) {
#pragma unroll
        for (int nt = 0; nt < 2; nt++) {
            int col = wn4 * 16 + nt * 8 + 2 * (lane & 3);
            float bia0 = b2[col], bia1 = b2[col + 1];
#pragma unroll
            for (int half = 0; half < 2; half++) {
                int row = wm * 64 + mt * 16 + (lane >> 2) + half * 8;
                float v0 = acc2[mt][nt][half * 2 + 0] + bia0;
                float v1 = acc2[mt][nt][half * 2 + 1] + bia1;
                v0 = (v0 > 0.f) ? (v0 + 1.f) : expf(v0);
                v1 = (v1 > 0.f) ? (v1 + 1.f) : expf(v1);
                h162 ph; ph.x = __float2half(v0); ph.y = __float2half(v1);
                *(h162*)&ka[(size_t)(row0 + row) * 64 + col] = ph;
            }
        }
    }
}

// ===================== kv context via tensor cores =========================
__global__ void __launch_bounds__(256, 4)
kv_tc(const h16* __restrict__ ka, const h16* __restrict__ v,
      float* __restrict__ kv, float* __restrict__ ksum) {
    extern __shared__ char sm[];
    const int bh = blockIdx.x;
    const int b = bh / HH, h = bh % HH;
    const int m0 = blockIdx.y * 256;
    const int tid = threadIdx.x;
    const int lane = tid & 31, wid = tid >> 5;
    const int wd = wid >> 1, we = wid & 1;
    const uint32_t smb = smem_u32(sm);

    float acc[4][4];
    float aks[4] = {0.f, 0.f, 0.f, 0.f};
#pragma unroll
    for (int i = 0; i < 4; i++)
#pragma unroll
        for (int j = 0; j < 4; j++) acc[i][j] = 0.f;

    const size_t vbase = (size_t)b * MMCTX * EE + (size_t)h * DD;
    const size_t kabase = ((size_t)b * MMCTX) * HH + h;

    auto load_tile = [&](int t, int buf) {
        const int m = m0 + t * 32;
        int r = tid >> 3, u = tid & 7;
        uint32_t off = SWZ128((uint32_t)(r * 128 + u * 16));
        cp_async16(smb + buf * 4096 + off,
                   ka + (kabase + (size_t)(m + r) * HH) * 64 + u * 8);
        cp_async16(smb + 8192 + buf * 4096 + off,
                   v + vbase + (size_t)(m + r) * EE + u * 8);
    };

    load_tile(0, 0);
    CP_COMMIT();

    const uint32_t ones[2] = {0x3C003C00u, 0x3C003C00u};

    for (int t = 0; t < 8; t++) {
        if (t + 1 < 8) {
            load_tile(t + 1, (t + 1) & 1);
            CP_COMMIT();
            CP_WAIT1();
        } else {
            CP_WAIT0();
        }
        __syncthreads();
        const uint32_t kas = smb + (t & 1) * 4096;
        const uint32_t vs = smb + 8192 + (t & 1) * 4096;
#pragma unroll
        for (int ks2 = 0; ks2 < 2; ks2++) {
            const int mb = ks2 * 16;
            uint32_t a[4];
            {
                int row = mb + ((lane >> 4) << 3) + (lane & 7);
                int cb = wd * 32 + (((lane >> 3) & 1) << 4);
                ldmatrix_x4t(kas + SWZ128((uint32_t)(row * 128 + cb)),
                             a[0], a[1], a[2], a[3]);
            }
            uint32_t bb[4][2];
#pragma unroll
            for (int p = 0; p < 2; p++) {
                int row = mb + (((lane >> 3) & 1) << 3) + (lane & 7);
                int cb = we * 64 + p * 32 + ((lane >> 4) << 4);
                uint32_t r0, r1, r2, r3;
                ldmatrix_x4t(vs + SWZ128((uint32_t)(row * 128 + cb)),
                             r0, r1, r2, r3);
                bb[2 * p][0] = r0; bb[2 * p][1] = r1;
                bb[2 * p + 1][0] = r2; bb[2 * p + 1][1] = r3;
            }
#pragma unroll
            for (int nt = 0; nt < 4; nt++) mma16816(acc[nt], a, bb[nt]);
            if (we == 0) mma16816(aks, a, ones);
        }
        __syncthreads();
    }

    const float inv_m = 1.f / (float)MMCTX;
    const int r0 = wd * 16 + (lane >> 2);
    float* kvb = kv + (size_t)bh * DD * DD;
#pragma unroll
    for (int nt = 0; nt < 4; nt++) {
        int col = we * 32 + nt * 8 + (lane & 3) * 2;
        atomicAdd(&kvb[r0 * DD + col], acc[nt][0] * inv_m);
        atomicAdd(&kvb[r0 * DD + col + 1], acc[nt][1] * inv_m);
        atomicAdd(&kvb[(r0 + 8) * DD + col], acc[nt][2] * inv_m);
        atomicAdd(&kvb[(r0 + 8) * DD + col + 1], acc[nt][3] * inv_m);
    }
    if (we == 0 && (lane & 3) == 0) {
        atomicAdd(&ksum[bh * DD + r0], aks[0] * inv_m);
        atomicAdd(&ksum[bh * DD + r0 + 8], aks[2] * inv_m);
    }
}

// ===================== out einsum via tensor cores =========================
__global__ void __launch_bounds__(256, 2)
out_tc(const h16* __restrict__ q, const float* __restrict__ kv,
       const float* __restrict__ ksum, h16* __restrict__ attn) {
    extern __shared__ char sm[];
    // qA 16K @0 ; Bkv fp16 8K @16384 ; kvs fp32 [64][68] @24576 (17408) ;
    // kss fp32 @41984 (256) ; den fp32 @42240 (512)  => 42752
    const int bh = blockIdx.x;
    const int b = bh / HH, h = bh % HH;
    const int n0 = blockIdx.y * 128;
    const int tid = threadIdx.x;
    const int lane = tid & 31, wid = tid >> 5;
    const int wm = wid >> 1, wn = wid & 1;
    const uint32_t smb = smem_u32(sm);
    float* kvs = (float*)(sm + 24576);
    float* kss = (float*)(sm + 41984);
    float* den = (float*)(sm + 42240);

    const size_t qbase = ((size_t)b * NN + n0) * EE + (size_t)h * DD;
#pragma unroll
    for (int i = 0; i < 4; i++) {
        int idx = tid + i * 256;
        int r = idx >> 3, u = idx & 7;
        cp_async16(smb + SWZ128((uint32_t)(r * 128 + u * 16)),
                   q + qbase + (size_t)r * EE + u * 8);
    }
    {
        const float* kvg = kv + (size_t)bh * DD * DD;
#pragma unroll
        for (int i = 0; i < 4; i++) {
            int j = (tid + i * 256) * 4;
            int d = j >> 6, e = j & 63;
            float4 val = *(const float4*)&kvg[j];
            *(float4*)&kvs[d * 68 + e] = val;
        }
    }
    if (tid < 16) {
        float4 val = *(const float4*)&ksum[bh * DD + tid * 4];
        *(float4*)&kss[tid * 4] = val;
    }
    CP_COMMIT();
    CP_WAIT0();
    __syncthreads();

    {
        int e = tid >> 2, db = (tid & 3) * 16;
#pragma unroll
        for (int dd2 = 0; dd2 < 16; dd2 += 2) {
            int d = db + dd2;
            h162 ph;
            ph.x = __float2half(kvs[d * 68 + e]);
            ph.y = __float2half(kvs[(d + 1) * 68 + e]);
            *(h162*)(sm + 16384 + SWZ128((uint32_t)(e * 128 + d * 2))) = ph;
        }
    }
    if (tid < 128) {
        float s = 0.f;
#pragma unroll
        for (int u = 0; u < 8; u++) {
            uint4 raw = *(const uint4*)(sm + SWZ128((uint32_t)(tid * 128 + u * 16)));
            const h162* hp = (const h162*)&raw;
#pragma unroll
            for (int j = 0; j < 4; j++) {
                float2 f = __half22float2(hp[j]);
                s += f.x * kss[u * 8 + j * 2] + f.y * kss[u * 8 + j * 2 + 1];
            }
        }
        den[tid] = fmaxf(s, 1e-6f);
    }
    __syncthreads();

    float acc[2][4][4];
#pragma unroll
    for (int i = 0; i < 2; i++)
#pragma unroll
        for (int j = 0; j < 4; j++)
#pragma unroll
            for (int t = 0; t < 4; t++) acc[i][j][t] = 0.f;

#pragma unroll
    for (int ks2 = 0; ks2 < 4; ks2++) {
        uint32_t ah[2][4], bb[4][2];
#pragma unroll
        for (int mt = 0; mt < 2; mt++) {
            int row = wm * 32 + mt * 16 + (lane & 15);
            int kb = ks2 * 32 + ((lane >> 4) << 4);
            ldmatrix_x4(smb + SWZ128((uint32_t)(row * 128 + kb)),
                        ah[mt][0], ah[mt][1], ah[mt][2], ah[mt][3]);
        }
#pragma unroll
        for (int p = 0; p < 2; p++) {
            int row = wn * 32 + p * 16 + ((lane >> 4) << 3) + (lane & 7);
            int kb = ks2 * 32 + (((lane & 15) >> 3) << 4);
            uint32_t r0, r1, r2, r3;
            ldmatrix_x4(smb + 16384 + SWZ128((uint32_t)(row * 128 + kb)),
                        r0, r1, r2, r3);
            bb[2 * p][0] = r0; bb[2 * p][1] = r1;
            bb[2 * p + 1][0] = r2; bb[2 * p + 1][1] = r3;
        }
#pragma unroll
        for (int mt = 0; mt < 2; mt++)
#pragma unroll
            for (int nt = 0; nt < 4; nt++) mma16816(acc[mt][nt], ah[mt], bb[nt]);
    }

#pragma unroll
    for (int mt = 0; mt < 2; mt++) {
#pragma unroll
        for (int nt = 0; nt < 4; nt++) {
            int col = wn * 32 + nt * 8 + (lane & 3) * 2;
#pragma unroll
            for (int half = 0; half < 2; half++) {
                int row = wm * 32 + mt * 16 + (lane >> 2) + half * 8;
                float rcp = 1.f / den[row];
                float v0 = acc[mt][nt][half * 2 + 0] * rcp;
                float v1 = acc[mt][nt][half * 2 + 1] * rcp;
                v0 = isnan(v0) ? 0.f : fminf(fmaxf(v0, -65000.f), 65000.f);
                v1 = isnan(v1) ? 0.f : fminf(fmaxf(v1, -65000.f), 65000.f);
                h162 ph; ph.x = __float2half(v0); ph.y = __float2half(v1);
                *(h162*)&attn[qbase + (size_t)row * EE + col] = ph;
            }
        }
    }
}

// ===================== launch =====================
extern "C" void kernel_launch(void* const* d_in, const int* in_sizes, int n_in,
                              void* d_out, int out_size) {
    const float* query = (const float*)d_in[0];
    const float* key   = (const float*)d_in[1];
    const float* value = (const float*)d_in[2];
    const float* Wq = (const float*)d_in[3];
    const float* bq = (const float*)d_in[4];
    const float* Wk = (const float*)d_in[5];
    const float* bk = (const float*)d_in[6];
    const float* Wv = (const float*)d_in[7];
    const float* bv = (const float*)d_in[8];
    const float* W1 = (const float*)d_in[9];
    const float* b1 = (const float*)d_in[10];
    const float* W2 = (const float*)d_in[11];
    const float* b2 = (const float*)d_in[12];
    const float* Wo = (const float*)d_in[13];
    const float* bo = (const float*)d_in[14];
    float* out = (float*)d_out;

    float *kv_s, *ksum_s;
    cudaGetSymbolAddress((void**)&kv_s, g_kv);
    cudaGetSymbolAddress((void**)&ksum_s, g_ksum);

    h16 *q16, *v16, *ka16, *kact, *attn, *Wqd, *Wkd, *Wvd, *Wod, *W1d, *W2d;
    cudaGetSymbolAddress((void**)&q16, g_q16);
    cudaGetSymbolAddress((void**)&v16, g_v16);
    cudaGetSymbolAddress((void**)&ka16, g_ka16);
    cudaGetSymbolAddress((void**)&kact, g_kact);
    cudaGetSymbolAddress((void**)&attn, g_attn);
    cudaGetSymbolAddress((void**)&Wqd, g_Wq);
    cudaGetSymbolAddress((void**)&Wkd, g_Wk);
    cudaGetSymbolAddress((void**)&Wvd, g_Wv);
    cudaGetSymbolAddress((void**)&Wod, g_Wo);
    cudaGetSymbolAddress((void**)&W1d, g_W1);
    cudaGetSymbolAddress((void**)&W2d, g_W2);

    const int SMQKV = 81920;
    const int SMH = 65536;
    const int SMM = 81920;
    const int SMKV = 16384;
    const int SMOUT = 42752;
    cudaFuncSetAttribute((const void*)mma_qkv,
                         cudaFuncAttributeMaxDynamicSharedMemorySize, SMQKV);
    cudaFuncSetAttribute((const void*)mma_gemmH,
                         cudaFuncAttributeMaxDynamicSharedMemorySize, SMH);
    cudaFuncSetAttribute((const void*)mlp_fused,
                         cudaFuncAttributeMaxDynamicSharedMemorySize, SMM);
    cudaFuncSetAttribute((const void*)kv_tc,
                         cudaFuncAttributeMaxDynamicSharedMemorySize, SMKV);
    cudaFuncSetAttribute((const void*)out_tc,
                         cudaFuncAttributeMaxDynamicSharedMemorySize, SMOUT);

    // ---- setup: all weight transposes + zero in one launch
    {
        dim3 blk(32, 8);
        setup_kernel<<<dim3(16, 16, 7), blk>>>(Wq, Wk, Wv, Wo, W1, W2,
                                               Wqd, Wkd, Wvd, Wod, W1d, W2d,
                                               kv_s, ksum_s);
    }
    // ---- merged Q/K/V projections (BK=32, own-thread conversion)
    {
        dim3 grid(EE / 128, ROWS_QK / 128, 3);
        mma_qkv<<<grid, 256, SMQKV>>>(query, key, value, Wqd, Wkd, Wvd,
                                      bq, bk, bv, q16, kact, v16);
    }
    // ---- fused key MLP
    mlp_fused<<<ROWS_MLP / 128, 256, SMM>>>(kact, W1d, W2d, b1, b2, ka16);
    // ---- kv context + ksum via tensor cores (256-row chunks)
    {
        dim3 gkv(BB * HH, MMCTX / 256);
        kv_tc<<<gkv, 256, SMKV>>>(ka16, v16, kv_s, ksum_s);
    }
    // ---- out einsum + normalize via tensor cores
    {
        dim3 go(BB * HH, NN / 128);
        out_tc<<<go, 256, SMOUT>>>(q16, kv_s, ksum_s, attn);
    }
    // ---- final projection
    {
        dim3 grid(EE / 128, ROWS_QK / 128);
        mma_gemmH<<<grid, 256, SMH>>>(attn, Wod, bo, out, EE, EE);
    }
}

// round 17
// speedup vs baseline: 1.1673x; 1.0492x over previous
#include <cuda_runtime.h>
#include <cuda_fp16.h>
#include <math.h>
#include <stdint.h>

#define BB 4
#define NN 4096
#define MMCTX 4096
#define EE 512
#define HH 8
#define DD 64
#define ROWS_QK (BB * NN)          // 16384
#define ROWS_MLP (BB * MMCTX * HH) // 131072

typedef __half h16;
typedef __half2 h162;

__device__ __forceinline__ uint32_t smem_u32(const void* p) {
    uint32_t a;
    asm("{ .reg .u64 t; cvta.to.shared.u64 t, %1; cvt.u32.u64 %0, t; }"
        : "=r"(a) : "l"(p));
    return a;
}

#define SWZ128(b) ((b) ^ (((b) >> 3) & 0x70))

__device__ __forceinline__ void cp_async16(uint32_t dst, const void* src) {
    asm volatile("cp.async.cg.shared.global [%0], [%1], 16;\n"
                 :: "r"(dst), "l"(src));
}
#define CP_COMMIT() asm volatile("cp.async.commit_group;\n" ::: "memory")
#define CP_WAIT1() asm volatile("cp.async.wait_group 1;\n" ::: "memory")
#define CP_WAIT0() asm volatile("cp.async.wait_group 0;\n" ::: "memory")

__device__ __forceinline__ void ldmatrix_x4(uint32_t addr, uint32_t& r0,
                                            uint32_t& r1, uint32_t& r2,
                                            uint32_t& r3) {
    asm volatile("ldmatrix.sync.aligned.m8n8.x4.shared.b16 {%0,%1,%2,%3}, [%4];"
                 : "=r"(r0), "=r"(r1), "=r"(r2), "=r"(r3) : "r"(addr));
}

__device__ __forceinline__ void ldmatrix_x4t(uint32_t addr, uint32_t& r0,
                                             uint32_t& r1, uint32_t& r2,
                                             uint32_t& r3) {
    asm volatile(
        "ldmatrix.sync.aligned.m8n8.x4.trans.shared.b16 {%0,%1,%2,%3}, [%4];"
        : "=r"(r0), "=r"(r1), "=r"(r2), "=r"(r3) : "r"(addr));
}

__device__ __forceinline__ void mma16816(float* c, const uint32_t* a,
                                         const uint32_t* b) {
    asm volatile(
        "mma.sync.aligned.m16n8k16.row.col.f32.f16.f16.f32 "
        "{%0,%1,%2,%3}, {%4,%5,%6,%7}, {%8,%9}, {%0,%1,%2,%3};"
        : "+f"(c[0]), "+f"(c[1]), "+f"(c[2]), "+f"(c[3])
        : "r"(a[0]), "r"(a[1]), "r"(a[2]), "r"(a[3]), "r"(b[0]), "r"(b[1]));
}

// ===================== scratch =====================
__device__ h16 g_q16[ROWS_QK * EE];
__device__ h16 g_v16[ROWS_QK * EE];
__device__ h16 g_ka16[ROWS_MLP * DD];
__device__ float g_kv[BB * HH * DD * DD];
__device__ float g_ksum[BB * HH * DD];

__device__ h16 g_attn[ROWS_QK * EE];

__device__ h16 g_Wq[EE * EE];
__device__ h16 g_Wk[EE * EE];
__device__ h16 g_Wv[EE * EE];
__device__ h16 g_Wo[EE * EE];
__device__ h16 g_W1[128 * 64];
__device__ h16 g_W2[64 * 128];

// ===================== one setup kernel: transposes + zero ================
__global__ void setup_kernel(const float* __restrict__ Wq, const float* __restrict__ Wk,
                             const float* __restrict__ Wv, const float* __restrict__ Wo,
                             const float* __restrict__ W1, const float* __restrict__ W2,
                             h16* __restrict__ oq, h16* __restrict__ ok,
                             h16* __restrict__ ov, h16* __restrict__ oo,
                             h16* __restrict__ o1, h16* __restrict__ o2,
                             float* __restrict__ kv, float* __restrict__ ksum) {
    const int z = blockIdx.z;
    const int tx = threadIdx.x, ty = threadIdx.y;  // 32 x 8
    if (z == 6) {
        int gid = (blockIdx.y * 16 + blockIdx.x) * 256 + ty * 32 + tx;
        for (int i = gid; i < BB * HH * DD * DD; i += 65536) kv[i] = 0.f;
        if (gid < BB * HH * DD) ksum[gid] = 0.f;
        return;
    }
    const float* W;
    h16* o;
    int K, N;
    switch (z) {
        case 0: W = Wq; o = oq; K = 512; N = 512; break;
        case 1: W = Wk; o = ok; K = 512; N = 512; break;
        case 2: W = Wv; o = ov; K = 512; N = 512; break;
        case 3: W = Wo; o = oo; K = 512; N = 512; break;
        case 4: W = W1; o = o1; K = 64;  N = 128; break;
        default: W = W2; o = o2; K = 128; N = 64; break;
    }
    const int n0 = blockIdx.x * 32, k0 = blockIdx.y * 32;
    if (n0 >= N || k0 >= K) return;
    __shared__ float t[32][33];
#pragma unroll
    for (int i = 0; i < 4; i++)
        t[ty + i * 8][tx] = W[(size_t)(k0 + ty + i * 8) * N + n0 + tx];
    __syncthreads();
#pragma unroll
    for (int i = 0; i < 4; i++)
        o[(size_t)(n0 + ty + i * 8) * K + k0 + tx] =
            __float2half(t[tx][ty + i * 8]);
}

// ===================== merged QKV projection GEMM + fused key MLP ==========
// z=0: q = elu(query@Wq+bq)+1 -> q16 plain
// z=1: kact = elu(key@Wk+bk)+1 (kept in smem), then per-head MLP:
//      ka = elu(gelu(kact@W1+b1)@W2+b2)+1 -> ka16 directly
// z=2: v = value@Wv+bv -> v16 plain
// smem: A32 2x16K @0 ; B 2x16K @32768 ; conv 16K @65536 ; W1 16K @81920 ;
//       W2 2x8K @98304  => 114688. post-mainloop reuse: kact head tiles
//       @0/@16384 ; h1 khf tiles @32768/@49152.
__global__ void __launch_bounds__(256, 2)
mma_qkv(const float* __restrict__ Aq, const float* __restrict__ Ak,
        const float* __restrict__ Av, const h16* __restrict__ Bq,
        const h16* __restrict__ Bk, const h16* __restrict__ Bv,
        const float* __restrict__ bq, const float* __restrict__ bk,
        const float* __restrict__ bv, const h16* __restrict__ W1,
        const h16* __restrict__ W2, const float* __restrict__ b1,
        const float* __restrict__ b2, h16* __restrict__ q16,
        h16* __restrict__ ka16, h16* __restrict__ v16) {
    extern __shared__ char sm[];
    const int z = blockIdx.z;
    const float* A = (z == 0) ? Aq : (z == 1) ? Ak : Av;
    const h16* B = (z == 0) ? Bq : (z == 1) ? Bk : Bv;
    const float* bias = (z == 0) ? bq : (z == 1) ? bk : bv;

    const int tid = threadIdx.x;
    const int lane = tid & 31, wid = tid >> 5;
    const int wm = wid >> 1, wn = wid & 1;
    const int row0 = blockIdx.y * 128;
    const int col0 = blockIdx.x * 128;
    const uint32_t smb = smem_u32(sm);
    constexpr int K = EE;
    constexpr int nc = K / 32;  // 16

    // W1/W2 preload for z==1 (own commit group, completes during mainloop)
    if (z == 1) {
#pragma unroll
        for (int i = 0; i < 4; i++) {
            int idx = tid + i * 256;
            int r = idx >> 3, u = idx & 7;
            cp_async16(smb + 81920 + SWZ128((uint32_t)(r * 128 + u * 16)),
                       W1 + r * 64 + u * 8);
        }
#pragma unroll
        for (int i = 0; i < 4; i++) {
            int idx = tid + i * 256;
            int n = idx >> 4, u = idx & 15;
            int khf = u >> 3, u2 = u & 7;
            cp_async16(smb + 98304 + khf * 8192 +
                           SWZ128((uint32_t)(n * 128 + u2 * 16)),
                       W2 + n * 128 + u * 8);
        }
    }
    CP_COMMIT();

    float acc[2][8][4];
#pragma unroll
    for (int i = 0; i < 2; i++)
#pragma unroll
        for (int j = 0; j < 8; j++)
#pragma unroll
            for (int t = 0; t < 4; t++) acc[i][j][t] = 0.f;

    auto load_stage = [&](int c, int buf) {
        uint32_t as = smb + buf * 16384;
        uint32_t bs = smb + 32768 + buf * 16384;
        const float* Ap = A + (size_t)row0 * K + c * 32;
        const h16* Bp = B + (size_t)col0 * K + c * 32;
#pragma unroll
        for (int i = 0; i < 4; i++) {
            int idx = tid + i * 256;
            int r = idx >> 3, u = idx & 7;
            cp_async16(as + SWZ128((uint32_t)(r * 128 + u * 16)),
                       Ap + (size_t)r * K + u * 4);
        }
#pragma unroll
        for (int i = 0; i < 2; i++) {
            int idx = tid + i * 256;
            int r = idx >> 2, u = idx & 3;
            cp_async16(bs + SWZ128((uint32_t)(r * 128 + u * 16)),
                       Bp + (size_t)r * K + u * 8);
        }
    };

    load_stage(0, 0);
    CP_COMMIT();

    for (int c = 0; c < nc; c++) {
        if (c + 1 < nc) {
            load_stage(c + 1, (c + 1) & 1);
            CP_COMMIT();
            CP_WAIT1();
        } else {
            CP_WAIT0();
        }
        // own-thread conversion: same idx->(r,u) map as loader
        {
            char* ap = sm + (c & 1) * 16384;
            char* cvp = sm + 65536;
#pragma unroll
            for (int i = 0; i < 4; i++) {
                int idx = tid + i * 256;
                int r = idx >> 3, u = idx & 7;
                float4 v4 = *(const float4*)(ap + SWZ128((uint32_t)(r * 128 + u * 16)));
                h162 p0; p0.x = __float2half(v4.x); p0.y = __float2half(v4.y);
                h162 p1; p1.x = __float2half(v4.z); p1.y = __float2half(v4.w);
                uint32_t d = SWZ128((uint32_t)(r * 128 + u * 8));
                *(h162*)(cvp + d) = p0;
                *(h162*)(cvp + d + 4) = p1;
            }
        }
        __syncthreads();
        const uint32_t cvb = smb + 65536;
        const uint32_t bsb = smb + 32768 + (c & 1) * 16384;
#pragma unroll
        for (int ks = 0; ks < 2; ks++) {
            uint32_t ah[2][4], bb[8][2];
#pragma unroll
            for (int mt = 0; mt < 2; mt++) {
                int row = wm * 32 + mt * 16 + (lane & 15);
                int kb = ks * 32 + ((lane >> 4) << 4);
                ldmatrix_x4(cvb + SWZ128((uint32_t)(row * 128 + kb)),
                            ah[mt][0], ah[mt][1], ah[mt][2], ah[mt][3]);
            }
#pragma unroll
            for (int p = 0; p < 4; p++) {
                int row = wn * 64 + p * 16 + ((lane >> 4) << 3) + (lane & 7);
                int kb = ks * 32 + (((lane & 15) >> 3) << 4);
                ldmatrix_x4(bsb + SWZ128((uint32_t)(row * 128 + kb)),
                            bb[2 * p][0], bb[2 * p][1], bb[2 * p + 1][0],
                            bb[2 * p + 1][1]);
            }
#pragma unroll
            for (int mt = 0; mt < 2; mt++)
#pragma unroll
                for (int nt = 0; nt < 8; nt++) mma16816(acc[mt][nt], ah[mt], bb[nt]);
        }
        __syncthreads();
    }

    // ---- projection epilogue ----
#pragma unroll
    for (int mt = 0; mt < 2; mt++) {
#pragma unroll
        for (int nt = 0; nt < 8; nt++) {
            int col = col0 + wn * 64 + nt * 8 + 2 * (lane & 3);
            float bia0 = bias[col], bia1 = bias[col + 1];
#pragma unroll
            for (int half = 0; half < 2; half++) {
                int row = row0 + wm * 32 + mt * 16 + (lane >> 2) + half * 8;
                float v0 = acc[mt][nt][half * 2 + 0] + bia0;
                float v1 = acc[mt][nt][half * 2 + 1] + bia1;
                if (z != 2) {
                    v0 = (v0 > 0.f) ? (v0 + 1.f) : expf(v0);
                    v1 = (v1 > 0.f) ? (v1 + 1.f) : expf(v1);
                }
                h162 ph; ph.x = __float2half(v0); ph.y = __float2half(v1);
                if (z == 1) {
                    // keep kact tile in smem: head sub-tiles @0 / @16384
                    int lc = col - col0;
                    int hd = lc >> 6, cc = lc & 63;
                    int lr = row - row0;
                    *(h162*)(sm + hd * 16384 +
                             SWZ128((uint32_t)(lr * 128 + cc * 2))) = ph;
                } else {
                    h16* dst = (z == 0) ? q16 : v16;
                    *(h162*)&dst[(size_t)row * EE + col] = ph;
                }
            }
        }
    }

    if (z != 1) return;
    __syncthreads();

    // ---- fused per-head MLP (2 heads per tile) ----
    const int wm4 = wid >> 2, wn4 = wid & 3;
    for (int hd = 0; hd < 2; hd++) {
        const uint32_t kbuf = smb + hd * 16384;
        // GEMM1: 128x128x64, gelu -> h1 smem @32768/@49152
        float acc1[4][4][4];
#pragma unroll
        for (int i = 0; i < 4; i++)
#pragma unroll
            for (int j = 0; j < 4; j++)
#pragma unroll
                for (int t = 0; t < 4; t++) acc1[i][j][t] = 0.f;

#pragma unroll
        for (int ks = 0; ks < 4; ks++) {
            uint32_t ah[4][4], bb[4][2];
#pragma unroll
            for (int mt = 0; mt < 4; mt++) {
                int row = wm4 * 64 + mt * 16 + (lane & 15);
                int kb = ks * 32 + ((lane >> 4) << 4);
                ldmatrix_x4(kbuf + SWZ128((uint32_t)(row * 128 + kb)),
                            ah[mt][0], ah[mt][1], ah[mt][2], ah[mt][3]);
            }
#pragma unroll
            for (int p = 0; p < 2; p++) {
                int row = wn4 * 32 + p * 16 + ((lane >> 4) << 3) + (lane & 7);
                int kb = ks * 32 + (((lane & 15) >> 3) << 4);
                ldmatrix_x4(smb + 81920 + SWZ128((uint32_t)(row * 128 + kb)),
                            bb[2 * p][0], bb[2 * p][1], bb[2 * p + 1][0],
                            bb[2 * p + 1][1]);
            }
#pragma unroll
            for (int mt = 0; mt < 4; mt++)
#pragma unroll
                for (int nt = 0; nt < 4; nt++) mma16816(acc1[mt][nt], ah[mt], bb[nt]);
        }

#pragma unroll
        for (int mt = 0; mt < 4; mt++) {
#pragma unroll
            for (int nt = 0; nt < 4; nt++) {
                int col = wn4 * 32 + nt * 8 + 2 * (lane & 3);
                float bia0 = b1[col], bia1 = b1[col + 1];
                int khf = col >> 6, cc = col & 63;
#pragma unroll
                for (int half = 0; half < 2; half++) {
                    int row = wm4 * 64 + mt * 16 + (lane >> 2) + half * 8;
                    float v0 = acc1[mt][nt][half * 2 + 0] + bia0;
                    float v1 = acc1[mt][nt][half * 2 + 1] + bia1;
                    v0 = 0.5f * v0 * (1.f + erff(v0 * 0.70710678118654752f));
                    v1 = 0.5f * v1 * (1.f + erff(v1 * 0.70710678118654752f));
                    h162 ph; ph.x = __float2half(v0); ph.y = __float2half(v1);
                    *(h162*)(sm + 32768 + khf * 16384 +
                             SWZ128((uint32_t)(row * 128 + cc * 2))) = ph;
                }
            }
        }
        __syncthreads();

        // GEMM2: 128x64x128, elu+1 -> ka16
        float acc2[4][2][4];
#pragma unroll
        for (int i = 0; i < 4; i++)
#pragma unroll
            for (int j = 0; j < 2; j++)
#pragma unroll
                for (int t = 0; t < 4; t++) acc2[i][j][t] = 0.f;

#pragma unroll
        for (int kstep = 0; kstep < 8; kstep++) {
            int khf = kstep >> 2, ks2 = kstep & 3;
            uint32_t ah[4][4], bb[2][2];
#pragma unroll
            for (int mt = 0; mt < 4; mt++) {
                int row = wm4 * 64 + mt * 16 + (lane & 15);
                int kb = ks2 * 32 + ((lane >> 4) << 4);
                ldmatrix_x4(smb + 32768 + khf * 16384 +
                                SWZ128((uint32_t)(row * 128 + kb)),
                            ah[mt][0], ah[mt][1], ah[mt][2], ah[mt][3]);
            }
            {
                int row = wn4 * 16 + ((lane >> 4) << 3) + (lane & 7);
                int kb = ks2 * 32 + (((lane & 15) >> 3) << 4);
                ldmatrix_x4(smb + 98304 + khf * 8192 +
                                SWZ128((uint32_t)(row * 128 + kb)),
                            bb[0][0], bb[0][1], bb[1][0], bb[1][1]);
            }
#pragma unroll
            for (int mt = 0; mt < 4; mt++)
#pragma unroll
                for (int nt = 0; nt < 2; nt++) mma16816(acc2[mt][nt], ah[mt], bb[nt]);
        }

        const int hglob = (col0 >> 6) + hd;
#pragma unroll
        for (int mt = 0; mt < 4; mt++) {
#pragma unroll
            for (int nt = 0; nt < 2; nt++) {
                int col = wn4 * 16 + nt * 8 + 2 * (lane & 3);
                float bia0 = b2[col], bia1 = b2[col + 1];
#pragma unroll
                for (int half = 0; half < 2; half++) {
                    int row = wm4 * 64 + mt * 16 + (lane >> 2) + half * 8;
                    float v0 = acc2[mt][nt][half * 2 + 0] + bia0;
                    float v1 = acc2[mt][nt][half * 2 + 1] + bia1;
                    v0 = (v0 > 0.f) ? (v0 + 1.f) : expf(v0);
                    v1 = (v1 > 0.f) ? (v1 + 1.f) : expf(v1);
                    h162 ph; ph.x = __float2half(v0); ph.y = __float2half(v1);
                    size_t rp = (size_t)(row0 + row) * HH + hglob;
                    *(h162*)&ka16[rp * 64 + col] = ph;
                }
            }
        }
        __syncthreads();
    }
}

// ===================== fp16 HMMA GEMM (attn @ Wo -> fp32 out) ==============
__global__ void __launch_bounds__(256, 2)
mma_gemmH(const h16* __restrict__ A, const h16* __restrict__ B,
          const float* __restrict__ bias, float* __restrict__ Cf, int Ntot,
          int K) {
    extern __shared__ char sm[];
    constexpr int STAGE = 2 * 16384;
    const int tid = threadIdx.x;
    const int lane = tid & 31, wid = tid >> 5;
    const int wm = wid >> 1, wn = wid & 1;
    const int row0 = blockIdx.y * 128;
    const int col0 = blockIdx.x * 128;
    const uint32_t smb = smem_u32(sm);
    const int nc = K / 64;

    float acc[2][8][4];
#pragma unroll
    for (int i = 0; i < 2; i++)
#pragma unroll
        for (int j = 0; j < 8; j++)
#pragma unroll
            for (int t = 0; t < 4; t++) acc[i][j][t] = 0.f;

    auto load_stage = [&](int c, int buf) {
        uint32_t as = smb + buf * STAGE;
        uint32_t bs = as + 16384;
        const h16* Ap = A + (size_t)row0 * K + c * 64;
        const h16* Bp = B + (size_t)col0 * K + c * 64;
#pragma unroll
        for (int i = 0; i < 4; i++) {
            int idx = tid + i * 256;
            int r = idx >> 3, u = idx & 7;
            uint32_t so = SWZ128((uint32_t)(r * 128 + u * 16));
            cp_async16(as + so, Ap + (size_t)r * K + u * 8);
            cp_async16(bs + so, Bp + (size_t)r * K + u * 8);
        }
    };

    load_stage(0, 0);
    CP_COMMIT();

    for (int c = 0; c < nc; c++) {
        if (c + 1 < nc) {
            load_stage(c + 1, (c + 1) & 1);
            CP_COMMIT();
            CP_WAIT1();
        } else {
            CP_WAIT0();
        }
        __syncthreads();
        uint32_t as = smb + (c & 1) * STAGE;
        uint32_t bs = as + 16384;
#pragma unroll
        for (int ks = 0; ks < 4; ks++) {
            uint32_t ah[2][4], bb[8][2];
#pragma unroll
            for (int mt = 0; mt < 2; mt++) {
                int row = wm * 32 + mt * 16 + (lane & 15);
                int kb = ks * 32 + ((lane >> 4) << 4);
                ldmatrix_x4(as + SWZ128((uint32_t)(row * 128 + kb)),
                            ah[mt][0], ah[mt][1], ah[mt][2], ah[mt][3]);
            }
#pragma unroll
            for (int p = 0; p < 4; p++) {
                int row = wn * 64 + p * 16 + ((lane >> 4) << 3) + (lane & 7);
                int kb = ks * 32 + (((lane & 15) >> 3) << 4);
                ldmatrix_x4(bs + SWZ128((uint32_t)(row * 128 + kb)),
                            bb[2 * p][0], bb[2 * p][1], bb[2 * p + 1][0],
                            bb[2 * p + 1][1]);
            }
#pragma unroll
            for (int mt = 0; mt < 2; mt++)
#pragma unroll
                for (int nt = 0; nt < 8; nt++) mma16816(acc[mt][nt], ah[mt], bb[nt]);
        }
        __syncthreads();
    }

#pragma unroll
    for (int mt = 0; mt < 2; mt++) {
#pragma unroll
        for (int nt = 0; nt < 8; nt++) {
            int col = col0 + wn * 64 + nt * 8 + 2 * (lane & 3);
            float bia0 = bias[col], bia1 = bias[col + 1];
#pragma unroll
            for (int half = 0; half < 2; half++) {
                int row = row0 + wm * 32 + mt * 16 + (lane >> 2) + half * 8;
                float v0 = acc[mt][nt][half * 2 + 0] + bia0;
                float v1 = acc[mt][nt][half * 2 + 1] + bia1;
                float2 o = make_float2(v0, v1);
                *(float2*)&Cf[(size_t)row * Ntot + col] = o;
            }
        }
    }
}

// ===================== kv context via tensor cores =========================
__global__ void __launch_bounds__(256, 4)
kv_tc(const h16* __restrict__ ka, const h16* __restrict__ v,
      float* __restrict__ kv, float* __restrict__ ksum) {
    extern __shared__ char sm[];
    const int bh = blockIdx.x;
    const int b = bh / HH, h = bh % HH;
    const int m0 = blockIdx.y * 256;
    const int tid = threadIdx.x;
    const int lane = tid & 31, wid = tid >> 5;
    const int wd = wid >> 1, we = wid & 1;
    const uint32_t smb = smem_u32(sm);

    float acc[4][4];
    float aks[4] = {0.f, 0.f, 0.f, 0.f};
#pragma unroll
    for (int i = 0; i < 4; i++)
#pragma unroll
        for (int j = 0; j < 4; j++) acc[i][j] = 0.f;

    const size_t vbase = (size_t)b * MMCTX * EE + (size_t)h * DD;
    const size_t kabase = ((size_t)b * MMCTX) * HH + h;

    auto load_tile = [&](int t, int buf) {
        const int m = m0 + t * 32;
        int r = tid >> 3, u = tid & 7;
        uint32_t off = SWZ128((uint32_t)(r * 128 + u * 16));
        cp_async16(smb + buf * 4096 + off,
                   ka + (kabase + (size_t)(m + r) * HH) * 64 + u * 8);
        cp_async16(smb + 8192 + buf * 4096 + off,
                   v + vbase + (size_t)(m + r) * EE + u * 8);
    };

    load_tile(0, 0);
    CP_COMMIT();

    const uint32_t ones[2] = {0x3C003C00u, 0x3C003C00u};

    for (int t = 0; t < 8; t++) {
        if (t + 1 < 8) {
            load_tile(t + 1, (t + 1) & 1);
            CP_COMMIT();
            CP_WAIT1();
        } else {
            CP_WAIT0();
        }
        __syncthreads();
        const uint32_t kas = smb + (t & 1) * 4096;
        const uint32_t vs = smb + 8192 + (t & 1) * 4096;
#pragma unroll
        for (int ks2 = 0; ks2 < 2; ks2++) {
            const int mb = ks2 * 16;
            uint32_t a[4];
            {
                int row = mb + ((lane >> 4) << 3) + (lane & 7);
                int cb = wd * 32 + (((lane >> 3) & 1) << 4);
                ldmatrix_x4t(kas + SWZ128((uint32_t)(row * 128 + cb)),
                             a[0], a[1], a[2], a[3]);
            }
            uint32_t bb[4][2];
#pragma unroll
            for (int p = 0; p < 2; p++) {
                int row = mb + (((lane >> 3) & 1) << 3) + (lane & 7);
                int cb = we * 64 + p * 32 + ((lane >> 4) << 4);
                uint32_t r0, r1, r2, r3;
                ldmatrix_x4t(vs + SWZ128((uint32_t)(row * 128 + cb)),
                             r0, r1, r2, r3);
                bb[2 * p][0] = r0; bb[2 * p][1] = r1;
                bb[2 * p + 1][0] = r2; bb[2 * p + 1][1] = r3;
            }
#pragma unroll
            for (int nt = 0; nt < 4; nt++) mma16816(acc[nt], a, bb[nt]);
            if (we == 0) mma16816(aks, a, ones);
        }
        __syncthreads();
    }

    const float inv_m = 1.f / (float)MMCTX;
    const int r0 = wd * 16 + (lane >> 2);
    float* kvb = kv + (size_t)bh * DD * DD;
#pragma unroll
    for (int nt = 0; nt < 4; nt++) {
        int col = we * 32 + nt * 8 + (lane & 3) * 2;
        atomicAdd(&kvb[r0 * DD + col], acc[nt][0] * inv_m);
        atomicAdd(&kvb[r0 * DD + col + 1], acc[nt][1] * inv_m);
        atomicAdd(&kvb[(r0 + 8) * DD + col], acc[nt][2] * inv_m);
        atomicAdd(&kvb[(r0 + 8) * DD + col + 1], acc[nt][3] * inv_m);
    }
    if (we == 0 && (lane & 3) == 0) {
        atomicAdd(&ksum[bh * DD + r0], aks[0] * inv_m);
        atomicAdd(&ksum[bh * DD + r0 + 8], aks[2] * inv_m);
    }
}

// ===================== out einsum via tensor cores =========================
__global__ void __launch_bounds__(256, 2)
out_tc(const h16* __restrict__ q, const float* __restrict__ kv,
       const float* __restrict__ ksum, h16* __restrict__ attn) {
    extern __shared__ char sm[];
    const int bh = blockIdx.x;
    const int b = bh / HH, h = bh % HH;
    const int n0 = blockIdx.y * 128;
    const int tid = threadIdx.x;
    const int lane = tid & 31, wid = tid >> 5;
    const int wm = wid >> 1, wn = wid & 1;
    const uint32_t smb = smem_u32(sm);
    float* kvs = (float*)(sm + 24576);
    float* kss = (float*)(sm + 41984);
    float* den = (float*)(sm + 42240);

    const size_t qbase = ((size_t)b * NN + n0) * EE + (size_t)h * DD;
#pragma unroll
    for (int i = 0; i < 4; i++) {
        int idx = tid + i * 256;
        int r = idx >> 3, u = idx & 7;
        cp_async16(smb + SWZ128((uint32_t)(r * 128 + u * 16)),
                   q + qbase + (size_t)r * EE + u * 8);
    }
    {
        const float* kvg = kv + (size_t)bh * DD * DD;
#pragma unroll
        for (int i = 0; i < 4; i++) {
            int j = (tid + i * 256) * 4;
            int d = j >> 6, e = j & 63;
            float4 val = *(const float4*)&kvg[j];
            *(float4*)&kvs[d * 68 + e] = val;
        }
    }
    if (tid < 16) {
        float4 val = *(const float4*)&ksum[bh * DD + tid * 4];
        *(float4*)&kss[tid * 4] = val;
    }
    CP_COMMIT();
    CP_WAIT0();
    __syncthreads();

    {
        int e = tid >> 2, db = (tid & 3) * 16;
#pragma unroll
        for (int dd2 = 0; dd2 < 16; dd2 += 2) {
            int d = db + dd2;
            h162 ph;
            ph.x = __float2half(kvs[d * 68 + e]);
            ph.y = __float2half(kvs[(d + 1) * 68 + e]);
            *(h162*)(sm + 16384 + SWZ128((uint32_t)(e * 128 + d * 2))) = ph;
        }
    }
    if (tid < 128) {
        float s = 0.f;
#pragma unroll
        for (int u = 0; u < 8; u++) {
            uint4 raw = *(const uint4*)(sm + SWZ128((uint32_t)(tid * 128 + u * 16)));
            const h162* hp = (const h162*)&raw;
#pragma unroll
            for (int j = 0; j < 4; j++) {
                float2 f = __half22float2(hp[j]);
                s += f.x * kss[u * 8 + j * 2] + f.y * kss[u * 8 + j * 2 + 1];
            }
        }
        den[tid] = fmaxf(s, 1e-6f);
    }
    __syncthreads();

    float acc[2][4][4];
#pragma unroll
    for (int i = 0; i < 2; i++)
#pragma unroll
        for (int j = 0; j < 4; j++)
#pragma unroll
            for (int t = 0; t < 4; t++) acc[i][j][t] = 0.f;

#pragma unroll
    for (int ks2 = 0; ks2 < 4; ks2++) {
        uint32_t ah[2][4], bb[4][2];
#pragma unroll
        for (int mt = 0; mt < 2; mt++) {
            int row = wm * 32 + mt * 16 + (lane & 15);
            int kb = ks2 * 32 + ((lane >> 4) << 4);
            ldmatrix_x4(smb + SWZ128((uint32_t)(row * 128 + kb)),
                        ah[mt][0], ah[mt][1], ah[mt][2], ah[mt][3]);
        }
#pragma unroll
        for (int p = 0; p < 2; p++) {
            int row = wn * 32 + p * 16 + ((lane >> 4) << 3) + (lane & 7);
            int kb = ks2 * 32 + (((lane & 15) >> 3) << 4);
            uint32_t r0, r1, r2, r3;
            ldmatrix_x4(smb + 16384 + SWZ128((uint32_t)(row * 128 + kb)),
                        r0, r1, r2, r3);
            bb[2 * p][0] = r0; bb[2 * p][1] = r1;
            bb[2 * p + 1][0] = r2; bb[2 * p + 1][1] = r3;
        }
#pragma unroll
        for (int mt = 0; mt < 2; mt++)
#pragma unroll
            for (int nt = 0; nt < 4; nt++) mma16816(acc[mt][nt], ah[mt], bb[nt]);
    }

#pragma unroll
    for (int mt = 0; mt < 2; mt++) {
#pragma unroll
        for (int nt = 0; nt < 4; nt++) {
            int col = wn * 32 + nt * 8 + (lane & 3) * 2;
#pragma unroll
            for (int half = 0; half < 2; half++) {
                int row = wm * 32 + mt * 16 + (lane >> 2) + half * 8;
                float rcp = 1.f / den[row];
                float v0 = acc[mt][nt][half * 2 + 0] * rcp;
                float v1 = acc[mt][nt][half * 2 + 1] * rcp;
                v0 = isnan(v0) ? 0.f : fminf(fmaxf(v0, -65000.f), 65000.f);
                v1 = isnan(v1) ? 0.f : fminf(fmaxf(v1, -65000.f), 65000.f);
                h162 ph; ph.x = __float2half(v0); ph.y = __float2half(v1);
                *(h162*)&attn[qbase + (size_t)row * EE + col] = ph;
            }
        }
    }
}

// ===================== launch =====================
extern "C" void kernel_launch(void* const* d_in, const int* in_sizes, int n_in,
                              void* d_out, int out_size) {
    const float* query = (const float*)d_in[0];
    const float* key   = (const float*)d_in[1];
    const float* value = (const float*)d_in[2];
    const float* Wq = (const float*)d_in[3];
    const float* bq = (const float*)d_in[4];
    const float* Wk = (const float*)d_in[5];
    const float* bk = (const float*)d_in[6];
    const float* Wv = (const float*)d_in[7];
    const float* bv = (const float*)d_in[8];
    const float* W1 = (const float*)d_in[9];
    const float* b1 = (const float*)d_in[10];
    const float* W2 = (const float*)d_in[11];
    const float* b2 = (const float*)d_in[12];
    const float* Wo = (const float*)d_in[13];
    const float* bo = (const float*)d_in[14];
    float* out = (float*)d_out;

    float *kv_s, *ksum_s;
    cudaGetSymbolAddress((void**)&kv_s, g_kv);
    cudaGetSymbolAddress((void**)&ksum_s, g_ksum);

    h16 *q16, *v16, *ka16, *attn, *Wqd, *Wkd, *Wvd, *Wod, *W1d, *W2d;
    cudaGetSymbolAddress((void**)&q16, g_q16);
    cudaGetSymbolAddress((void**)&v16, g_v16);
    cudaGetSymbolAddress((void**)&ka16, g_ka16);
    cudaGetSymbolAddress((void**)&attn, g_attn);
    cudaGetSymbolAddress((void**)&Wqd, g_Wq);
    cudaGetSymbolAddress((void**)&Wkd, g_Wk);
    cudaGetSymbolAddress((void**)&Wvd, g_Wv);
    cudaGetSymbolAddress((void**)&Wod, g_Wo);
    cudaGetSymbolAddress((void**)&W1d, g_W1);
    cudaGetSymbolAddress((void**)&W2d, g_W2);

    const int SMQKV = 114688;
    const int SMH = 65536;
    const int SMKV = 16384;
    const int SMOUT = 42752;
    cudaFuncSetAttribute((const void*)mma_qkv,
                         cudaFuncAttributeMaxDynamicSharedMemorySize, SMQKV);
    cudaFuncSetAttribute((const void*)mma_gemmH,
                         cudaFuncAttributeMaxDynamicSharedMemorySize, SMH);
    cudaFuncSetAttribute((const void*)kv_tc,
                         cudaFuncAttributeMaxDynamicSharedMemorySize, SMKV);
    cudaFuncSetAttribute((const void*)out_tc,
                         cudaFuncAttributeMaxDynamicSharedMemorySize, SMOUT);

    // ---- setup: all weight transposes + zero in one launch
    {
        dim3 blk(32, 8);
        setup_kernel<<<dim3(16, 16, 7), blk>>>(Wq, Wk, Wv, Wo, W1, W2,
                                               Wqd, Wkd, Wvd, Wod, W1d, W2d,
                                               kv_s, ksum_s);
    }
    // ---- merged Q/K/V projections + fused key MLP
    {
        dim3 grid(EE / 128, ROWS_QK / 128, 3);
        mma_qkv<<<grid, 256, SMQKV>>>(query, key, value, Wqd, Wkd, Wvd,
                                      bq, bk, bv, W1d, W2d, b1, b2,
                                      q16, ka16, v16);
    }
    // ---- kv context + ksum via tensor cores (256-row chunks)
    {
        dim3 gkv(BB * HH, MMCTX / 256);
        kv_tc<<<gkv, 256, SMKV>>>(ka16, v16, kv_s, ksum_s);
    }
    // ---- out einsum + normalize via tensor cores
    {
        dim3 go(BB * HH, NN / 128);
        out_tc<<<go, 256, SMOUT>>>(q16, kv_s, ksum_s, attn);
    }
    // ---- final projection
    {
        dim3 grid(EE / 128, ROWS_QK / 128);
        mma_gemmH<<<grid, 256, SMH>>>(attn, Wod, bo, out, EE, EE);
    }
}